// round 7
// baseline (speedup 1.0000x reference)
#include <cuda_runtime.h>
#include <cstddef>

#define B_    8
#define L_    4096
#define C_    1024
#define D_    1024
#define N_    256
#define MLP_  512
#define TIT_  6

// ---------------- scratch (device globals; no allocation allowed) ----------
__device__ float g_xn  [(size_t)B_ * L_ * C_];
__device__ float g_kv  [(size_t)B_ * L_ * 2 * D_];   // [l, 0:1024]=K, [l,1024:2048]=V
__device__ float g_attn[(size_t)B_ * L_ * N_];
__device__ float g_tmpl[B_ * N_ * D_];
__device__ float g_t   [B_ * N_ * D_];
__device__ float g_q   [B_ * N_ * D_];
__device__ float g_m   [B_ * N_ * D_];
__device__ float g_h   [B_ * N_ * MLP_];
__device__ float g_upd [B_ * N_ * D_];
__device__ float g_cs  [B_ * N_];
__device__ float g_wq  [D_ * D_];
__device__ float g_wkv [C_ * 2 * D_];
__device__ float g_w1  [D_ * MLP_];
__device__ float g_w2  [MLP_ * D_];

// ---------------- tf32 helpers ---------------------------------------------
__device__ __forceinline__ float to_tf32(float x) {
    unsigned u;
    asm("cvt.rna.tf32.f32 %0, %1;" : "=r"(u) : "f"(x));
    return __uint_as_float(u);
}

__device__ __forceinline__ void cp16(void* smem_dst, const void* gmem_src) {
    unsigned s = (unsigned)__cvta_generic_to_shared(smem_dst);
    asm volatile("cp.async.cg.shared.global [%0], [%1], 16;\n"
                 :: "r"(s), "l"(gmem_src));
}

// ---------------- tf32 tensor-core GEMM, cp.async double-buffered -----------
// C[M,N] = alpha*op(A)op(B) (+bias)(relu)(+resid) | atomic partials | fused softmax
// TA==0: A is [M,K].  TA==1: A is [K,M].   TB==0: B is [K,N].  TB==1: B is [N,K].
// CTA tile BM x BN x 32; warp tile fixed 64x64 (m16n8k8); threads = BM/64*BN/64*32.
// SMAX: BM=64, BN=N=256 required; writes softmax(row)+1e-8 and atomic colsum
//       into 'bias' (cast) at [batch*256 + col].
template<int BM, int BN, int TA, int TB, int BIAS, int RELU, int RESID, int CVT,
         int SPLITK, int ATOMIC, int SMAX>
__global__ void __launch_bounds__((BM / 64) * (BN / 64) * 32, 2) tgemm(
    const float* __restrict__ A, const float* __restrict__ Bm,
    const float* __restrict__ bias, const float* __restrict__ Rm,
    float* __restrict__ Cm,
    int M, int N, int K, int lda, int ldb, int ldc,
    long long sA, long long sB, long long sC, float alpha)
{
    constexpr int WM = BM / 64, WN = BN / 64;
    constexpr int THREADS = WM * WN * 32;
    constexpr int AST = (TA == 0) ? BM * 36 : 32 * (BM + 8);
    constexpr int BST = (TB == 0) ? 32 * (BN + 8) : BN * 36;
    constexpr int NA = BM * 8 / THREADS;
    constexpr int NB = BN * 8 / THREADS;
    extern __shared__ float sm[];
    float* As = sm;
    float* Bs = sm + 2 * AST;

    int bz = blockIdx.z, batch = bz, koff = 0;
    if (SPLITK > 1) { batch = bz / SPLITK; koff = (bz % SPLITK) * (K / SPLITK); }
    A  += (size_t)batch * sA + (TA ? (size_t)koff * lda : (size_t)koff);
    Bm += (size_t)batch * sB + (TB ? (size_t)koff : (size_t)koff * ldb);
    Cm += (size_t)batch * sC;
    const float* Rp = RESID ? (Rm + (size_t)batch * sC) : nullptr;

    const int m0 = blockIdx.y * BM, n0 = blockIdx.x * BN;
    const int tid = threadIdx.x, lane = tid & 31, wid = tid >> 5;
    const int wm = (wid % WM) * 64, wn = (wid / WM) * 64;
    const int g = lane >> 2, tig = lane & 3;

    float acc[4][8][4] = {};

    auto load_stage = [&](int k0, int s) {
        float* Ad = As + s * AST;
        float* Bd = Bs + s * BST;
#pragma unroll
        for (int i = 0; i < NA; i++) {
            const int idx = tid + i * THREADS;
            if (TA == 0) {
                const int row = idx >> 3, kc = (idx & 7) * 4;
                cp16(Ad + row * 36 + kc, A + (size_t)(m0 + row) * lda + k0 + kc);
            } else {
                const int kk = idx / (BM / 4), mc = (idx % (BM / 4)) * 4;
                cp16(Ad + kk * (BM + 8) + mc, A + (size_t)(k0 + kk) * lda + m0 + mc);
            }
        }
#pragma unroll
        for (int i = 0; i < NB; i++) {
            const int idx = tid + i * THREADS;
            if (TB == 0) {
                const int kk = idx / (BN / 4), nc = (idx % (BN / 4)) * 4;
                cp16(Bd + kk * (BN + 8) + nc, Bm + (size_t)(k0 + kk) * ldb + n0 + nc);
            } else {
                const int row = idx >> 3, kc = (idx & 7) * 4;
                cp16(Bd + row * 36 + kc, Bm + (size_t)(n0 + row) * ldb + k0 + kc);
            }
        }
        asm volatile("cp.async.commit_group;\n");
    };

    auto compute = [&](int s) {
        const float* Ab = As + s * AST;
        const float* Bb = Bs + s * BST;
#pragma unroll
        for (int ks = 0; ks < 4; ks++) {
            const int kb = ks * 8;
            unsigned a[4][4], b[8][2];
#pragma unroll
            for (int mt = 0; mt < 4; mt++) {
                const int row = wm + mt * 16 + g;
                if (TA == 0) {
                    const int base = row * 36 + kb + tig;
                    a[mt][0] = __float_as_uint(Ab[base]);
                    a[mt][1] = __float_as_uint(Ab[base + 8 * 36]);
                    a[mt][2] = __float_as_uint(Ab[base + 4]);
                    a[mt][3] = __float_as_uint(Ab[base + 8 * 36 + 4]);
                } else {
                    const int base = (kb + tig) * (BM + 8) + row;
                    a[mt][0] = __float_as_uint(Ab[base]);
                    a[mt][1] = __float_as_uint(Ab[base + 8]);
                    a[mt][2] = __float_as_uint(Ab[base + 4 * (BM + 8)]);
                    a[mt][3] = __float_as_uint(Ab[base + 4 * (BM + 8) + 8]);
                }
            }
#pragma unroll
            for (int nt = 0; nt < 8; nt++) {
                const int col = wn + nt * 8 + g;
                if (TB == 0) {
                    b[nt][0] = __float_as_uint(Bb[(kb + tig) * (BN + 8) + col]);
                    b[nt][1] = __float_as_uint(Bb[(kb + tig + 4) * (BN + 8) + col]);
                } else {
                    b[nt][0] = __float_as_uint(Bb[col * 36 + kb + tig]);
                    b[nt][1] = __float_as_uint(Bb[col * 36 + kb + tig + 4]);
                }
            }
#pragma unroll
            for (int mt = 0; mt < 4; mt++)
#pragma unroll
                for (int nt = 0; nt < 8; nt++)
                    asm volatile(
                        "mma.sync.aligned.m16n8k8.row.col.f32.tf32.tf32.f32 "
                        "{%0,%1,%2,%3}, {%4,%5,%6,%7}, {%8,%9}, {%0,%1,%2,%3};"
                        : "+f"(acc[mt][nt][0]), "+f"(acc[mt][nt][1]),
                          "+f"(acc[mt][nt][2]), "+f"(acc[mt][nt][3])
                        : "r"(a[mt][0]), "r"(a[mt][1]), "r"(a[mt][2]), "r"(a[mt][3]),
                          "r"(b[nt][0]), "r"(b[nt][1]));
        }
    };

    load_stage(0, 0);
    const int T = ((SPLITK > 1) ? K / SPLITK : K) >> 5;
    for (int t = 0; t < T; t++) {
        asm volatile("cp.async.wait_group 0;\n");
        __syncthreads();
        if (t + 1 < T) load_stage((t + 1) << 5, (t + 1) & 1);
        compute(t & 1);
    }

    if (SMAX) {
        // BM=64, WM=1: each warp owns all 64 rows x its 64 cols. Full row in CTA.
        float* red = sm;                        // [64][WN]
        float fmx[4][2], fsm[4][2];
        __syncthreads();
        // ---- row max ----
#pragma unroll
        for (int mt = 0; mt < 4; mt++) {
            float h0 = -1e30f, h1 = -1e30f;
#pragma unroll
            for (int nt = 0; nt < 8; nt++) {
                h0 = fmaxf(h0, fmaxf(acc[mt][nt][0], acc[mt][nt][1]));
                h1 = fmaxf(h1, fmaxf(acc[mt][nt][2], acc[mt][nt][3]));
            }
            h0 = fmaxf(h0, __shfl_xor_sync(0xffffffffu, h0, 1));
            h0 = fmaxf(h0, __shfl_xor_sync(0xffffffffu, h0, 2));
            h1 = fmaxf(h1, __shfl_xor_sync(0xffffffffu, h1, 1));
            h1 = fmaxf(h1, __shfl_xor_sync(0xffffffffu, h1, 2));
            fmx[mt][0] = h0; fmx[mt][1] = h1;
        }
        if (tig == 0)
#pragma unroll
            for (int mt = 0; mt < 4; mt++) {
                red[(mt * 16 + g) * WN + wid] = fmx[mt][0];
                red[(mt * 16 + g + 8) * WN + wid] = fmx[mt][1];
            }
        __syncthreads();
#pragma unroll
        for (int mt = 0; mt < 4; mt++) {
            float h0 = -1e30f, h1 = -1e30f;
#pragma unroll
            for (int w = 0; w < WN; w++) {
                h0 = fmaxf(h0, red[(mt * 16 + g) * WN + w]);
                h1 = fmaxf(h1, red[(mt * 16 + g + 8) * WN + w]);
            }
            fmx[mt][0] = h0; fmx[mt][1] = h1;
        }
        __syncthreads();
        // ---- exp + row sum ----
#pragma unroll
        for (int mt = 0; mt < 4; mt++) {
            float s0 = 0.f, s1 = 0.f;
#pragma unroll
            for (int nt = 0; nt < 8; nt++) {
                acc[mt][nt][0] = __expf(acc[mt][nt][0] - fmx[mt][0]);
                acc[mt][nt][1] = __expf(acc[mt][nt][1] - fmx[mt][0]);
                acc[mt][nt][2] = __expf(acc[mt][nt][2] - fmx[mt][1]);
                acc[mt][nt][3] = __expf(acc[mt][nt][3] - fmx[mt][1]);
                s0 += acc[mt][nt][0] + acc[mt][nt][1];
                s1 += acc[mt][nt][2] + acc[mt][nt][3];
            }
            s0 += __shfl_xor_sync(0xffffffffu, s0, 1);
            s0 += __shfl_xor_sync(0xffffffffu, s0, 2);
            s1 += __shfl_xor_sync(0xffffffffu, s1, 1);
            s1 += __shfl_xor_sync(0xffffffffu, s1, 2);
            fsm[mt][0] = s0; fsm[mt][1] = s1;
        }
        if (tig == 0)
#pragma unroll
            for (int mt = 0; mt < 4; mt++) {
                red[(mt * 16 + g) * WN + wid] = fsm[mt][0];
                red[(mt * 16 + g + 8) * WN + wid] = fsm[mt][1];
            }
        __syncthreads();
#pragma unroll
        for (int mt = 0; mt < 4; mt++) {
            float s0 = 0.f, s1 = 0.f;
#pragma unroll
            for (int w = 0; w < WN; w++) {
                s0 += red[(mt * 16 + g) * WN + w];
                s1 += red[(mt * 16 + g + 8) * WN + w];
            }
            fsm[mt][0] = 1.f / s0; fsm[mt][1] = 1.f / s1;
        }
        // ---- a = e/sum + 1e-8: store + column partial sums ----
        float csum[8][2];
#pragma unroll
        for (int nt = 0; nt < 8; nt++) { csum[nt][0] = 0.f; csum[nt][1] = 0.f; }
#pragma unroll
        for (int mt = 0; mt < 4; mt++) {
            const int r0 = m0 + mt * 16 + g, r1 = r0 + 8;
#pragma unroll
            for (int nt = 0; nt < 8; nt++) {
                const int c = n0 + wn + nt * 8 + tig * 2;
                const float a0 = acc[mt][nt][0] * fsm[mt][0] + 1e-8f;
                const float a1 = acc[mt][nt][1] * fsm[mt][0] + 1e-8f;
                const float a2 = acc[mt][nt][2] * fsm[mt][1] + 1e-8f;
                const float a3 = acc[mt][nt][3] * fsm[mt][1] + 1e-8f;
                float2 o0; o0.x = a0; o0.y = a1;
                float2 o1; o1.x = a2; o1.y = a3;
                *(float2*)(Cm + (size_t)r0 * ldc + c) = o0;
                *(float2*)(Cm + (size_t)r1 * ldc + c) = o1;
                csum[nt][0] += a0 + a2;
                csum[nt][1] += a1 + a3;
            }
        }
        float* csp = (float*)bias + batch * N_;
#pragma unroll
        for (int nt = 0; nt < 8; nt++) {
            float s0 = csum[nt][0], s1 = csum[nt][1];
            s0 += __shfl_xor_sync(0xffffffffu, s0, 4);
            s0 += __shfl_xor_sync(0xffffffffu, s0, 8);
            s0 += __shfl_xor_sync(0xffffffffu, s0, 16);
            s1 += __shfl_xor_sync(0xffffffffu, s1, 4);
            s1 += __shfl_xor_sync(0xffffffffu, s1, 8);
            s1 += __shfl_xor_sync(0xffffffffu, s1, 16);
            if (lane < 4) {
                const int c = n0 + wn + nt * 8 + lane * 2;
                atomicAdd(csp + c, s0);
                atomicAdd(csp + c + 1, s1);
            }
        }
        return;
    }

#pragma unroll
    for (int mt = 0; mt < 4; mt++) {
        const int r0 = m0 + wm + mt * 16 + g, r1 = r0 + 8;
#pragma unroll
        for (int nt = 0; nt < 8; nt++) {
            const int c = n0 + wn + nt * 8 + tig * 2;
            float v0 = acc[mt][nt][0] * alpha, v1 = acc[mt][nt][1] * alpha;
            float v2 = acc[mt][nt][2] * alpha, v3 = acc[mt][nt][3] * alpha;
            if (ATOMIC) {
                atomicAdd(Cm + (size_t)r0 * ldc + c,     v0);
                atomicAdd(Cm + (size_t)r0 * ldc + c + 1, v1);
                atomicAdd(Cm + (size_t)r1 * ldc + c,     v2);
                atomicAdd(Cm + (size_t)r1 * ldc + c + 1, v3);
                continue;
            }
            if (BIAS) {
                const float bx = bias[c], by = bias[c + 1];
                v0 += bx; v1 += by; v2 += bx; v3 += by;
            }
            if (RELU) {
                v0 = fmaxf(v0, 0.f); v1 = fmaxf(v1, 0.f);
                v2 = fmaxf(v2, 0.f); v3 = fmaxf(v3, 0.f);
            }
            if (RESID) {
                const float2 p = *(const float2*)(Rp + (size_t)r0 * ldc + c);
                const float2 q = *(const float2*)(Rp + (size_t)r1 * ldc + c);
                v0 += p.x; v1 += p.y; v2 += q.x; v3 += q.y;
            }
            if (CVT) {
                v0 = to_tf32(v0); v1 = to_tf32(v1);
                v2 = to_tf32(v2); v3 = to_tf32(v3);
            }
            float2 o0; o0.x = v0; o0.y = v1;
            float2 o1; o1.x = v2; o1.y = v3;
            *(float2*)(Cm + (size_t)r0 * ldc + c) = o0;
            *(float2*)(Cm + (size_t)r1 * ldc + c) = o1;
        }
    }
}

// ---------------- LayerNorm over 1024-wide rows (tf32-rounded output) -------
__global__ void __launch_bounds__(256) ln1024(
    const float* __restrict__ in, const float* __restrict__ g,
    const float* __restrict__ b, float* __restrict__ out)
{
    __shared__ float sh[8];
    __shared__ float s_mean, s_rstd;
    const size_t row = blockIdx.x;
    const int t = threadIdx.x;
    const float4 v = ((const float4*)(in + row * 1024))[t];

    float s = v.x + v.y + v.z + v.w;
#pragma unroll
    for (int o = 16; o; o >>= 1) s += __shfl_xor_sync(0xffffffffu, s, o);
    if ((t & 31) == 0) sh[t >> 5] = s;
    __syncthreads();
    if (t == 0) {
        float tt = 0.f;
#pragma unroll
        for (int i = 0; i < 8; i++) tt += sh[i];
        s_mean = tt * (1.f / 1024.f);
    }
    __syncthreads();
    const float mean = s_mean;
    const float dx = v.x - mean, dy = v.y - mean, dz = v.z - mean, dw = v.w - mean;

    float q = dx * dx + dy * dy + dz * dz + dw * dw;
#pragma unroll
    for (int o = 16; o; o >>= 1) q += __shfl_xor_sync(0xffffffffu, q, o);
    __syncthreads();
    if ((t & 31) == 0) sh[t >> 5] = q;
    __syncthreads();
    if (t == 0) {
        float tt = 0.f;
#pragma unroll
        for (int i = 0; i < 8; i++) tt += sh[i];
        s_rstd = rsqrtf(tt * (1.f / 1024.f) + 1e-5f);
    }
    __syncthreads();
    const float rstd = s_rstd;

    const float4 gv = ((const float4*)g)[t];
    const float4 bv = ((const float4*)b)[t];
    float4 o;
    o.x = to_tf32(dx * rstd * gv.x + bv.x);
    o.y = to_tf32(dy * rstd * gv.y + bv.y);
    o.z = to_tf32(dz * rstd * gv.z + bv.z);
    o.w = to_tf32(dw * rstd * gv.w + bv.w);
    ((float4*)(out + row * 1024))[t] = o;
}

__global__ void renorm_div(float* __restrict__ attn, const float* __restrict__ colsum)
{
    const size_t row = blockIdx.x;
    const int n = threadIdx.x;
    attn[row * 256 + n] /= colsum[(row >> 12) * 256 + n];
}

// zero colsum [B*N] and upd [B*N*D] (float4 stores)
__global__ void zero_scratch(float* __restrict__ upd, float* __restrict__ cs)
{
    const size_t i = (size_t)blockIdx.x * 256 + threadIdx.x;
    ((float4*)upd)[i] = make_float4(0.f, 0.f, 0.f, 0.f);
    if (i < B_ * N_) cs[i] = 0.f;
}

// tmpl += upd / colsum[row]  (the folded L-renorm)
__global__ void apply_update(float* __restrict__ tmpl, const float* __restrict__ upd,
                             const float* __restrict__ cs)
{
    const size_t i = (size_t)blockIdx.x * 256 + threadIdx.x;
    const int row = (int)(i / (D_ / 4));
    const float s = 1.f / cs[row];
    const float4 u = ((const float4*)upd)[i];
    float4 t = ((float4*)tmpl)[i];
    t.x += u.x * s; t.y += u.y * s; t.z += u.z * s; t.w += u.w * s;
    ((float4*)tmpl)[i] = t;
}

// ---------------- tiled transpose: per batch [R,Cc] -> [Cc,R] --------------
__global__ void transpose_k(const float* __restrict__ in, float* __restrict__ out,
                            int R, int Cc)
{
    __shared__ float tile[32][33];
    const size_t base = (size_t)blockIdx.z * R * Cc;
    const int c0 = blockIdx.x * 32, r0 = blockIdx.y * 32;
#pragma unroll
    for (int i = threadIdx.y; i < 32; i += 8)
        tile[i][threadIdx.x] = in[base + (size_t)(r0 + i) * Cc + c0 + threadIdx.x];
    __syncthreads();
#pragma unroll
    for (int i = threadIdx.y; i < 32; i += 8)
        out[base + (size_t)(c0 + i) * R + r0 + threadIdx.x] = tile[threadIdx.x][i];
}

__global__ void bcast_tmpl(const float* __restrict__ tinit, float* __restrict__ tmpl)
{
    const size_t i = (size_t)blockIdx.x * 256 + threadIdx.x;
    tmpl[i] = tinit[i & ((size_t)N_ * D_ - 1)];
}

__global__ void round_copy(const float* __restrict__ in, float* __restrict__ out)
{
    const size_t i = (size_t)blockIdx.x * 256 + threadIdx.x;
    out[i] = to_tf32(in[i]);
}

// wkv[k][j] = tf32(j<1024 ? Wk[k][j] : Wv[k][j-1024])
__global__ void pack_wkv(const float* __restrict__ Wk, const float* __restrict__ Wv,
                         float* __restrict__ wkv)
{
    const size_t i = (size_t)blockIdx.x * 256 + threadIdx.x;
    const int k = (int)(i >> 11), j = (int)(i & 2047);
    const float v = (j < D_) ? Wk[k * D_ + j] : Wv[k * D_ + j - D_];
    wkv[i] = to_tf32(v);
}

// ---------------- host orchestration ---------------------------------------
extern "C" void kernel_launch(void* const* d_in, const int* in_sizes, int n_in,
                              void* d_out, int out_size)
{
    const float* x       = (const float*)d_in[0];
    const float* tinit   = (const float*)d_in[1];
    const float* Wq      = (const float*)d_in[2];
    const float* Wk      = (const float*)d_in[3];
    const float* Wv      = (const float*)d_in[4];
    const float* ln_in_g = (const float*)d_in[5];
    const float* ln_in_b = (const float*)d_in[6];
    const float* ln_t_g  = (const float*)d_in[7];
    const float* ln_t_b  = (const float*)d_in[8];
    const float* ln_m_g  = (const float*)d_in[9];
    const float* ln_m_b  = (const float*)d_in[10];
    const float* W1      = (const float*)d_in[11];
    const float* b1      = (const float*)d_in[12];
    const float* W2      = (const float*)d_in[13];
    const float* b2      = (const float*)d_in[14];
    float* out = (float*)d_out;

    float *xn, *kv, *attn, *tmpl, *tb, *qb, *mb, *hb, *upd, *cs;
    float *wq, *wkv, *w1, *w2;
    cudaGetSymbolAddress((void**)&xn,   g_xn);
    cudaGetSymbolAddress((void**)&kv,   g_kv);
    cudaGetSymbolAddress((void**)&attn, g_attn);
    cudaGetSymbolAddress((void**)&tmpl, g_tmpl);
    cudaGetSymbolAddress((void**)&tb,   g_t);
    cudaGetSymbolAddress((void**)&qb,   g_q);
    cudaGetSymbolAddress((void**)&mb,   g_m);
    cudaGetSymbolAddress((void**)&hb,   g_h);
    cudaGetSymbolAddress((void**)&upd,  g_upd);
    cudaGetSymbolAddress((void**)&cs,   g_cs);
    cudaGetSymbolAddress((void**)&wq,   g_wq);
    cudaGetSymbolAddress((void**)&wkv,  g_wkv);
    cudaGetSymbolAddress((void**)&w1,   g_w1);
    cudaGetSymbolAddress((void**)&w2,   g_w2);

    // smem sizes: 2*(AST+BST)*4 bytes
    const int SM_KV  = 2 * (128 * 36 + 32 * 264) * 4;   // 104448  BM128 BN256 TA0 TB0
    const int SM_LOG = 2 * (64 * 36 + 256 * 36) * 4;    // 92160   BM64  BN256 TA0 TB1
    const int SM_UPD = 2 * (32 * 136 + 32 * 264) * 4;   // 102400  BM128 BN256 TA1 TB0
    const int SM_64  = 2 * (64 * 36 + 32 * 264) * 4;    // 86016   BM64  BN256 TA0 TB0

    cudaFuncSetAttribute(tgemm<128,256,0,0,0,0,0,1,1,0,0>, cudaFuncAttributeMaxDynamicSharedMemorySize, SM_KV);
    cudaFuncSetAttribute(tgemm<64,256,0,1,0,0,0,0,1,0,1>,  cudaFuncAttributeMaxDynamicSharedMemorySize, SM_LOG);
    cudaFuncSetAttribute(tgemm<128,256,1,0,0,0,0,0,4,1,0>, cudaFuncAttributeMaxDynamicSharedMemorySize, SM_UPD);
    cudaFuncSetAttribute(tgemm<64,256,0,0,0,0,0,1,1,0,0>,  cudaFuncAttributeMaxDynamicSharedMemorySize, SM_64);
    cudaFuncSetAttribute(tgemm<64,256,0,0,1,1,0,1,1,0,0>,  cudaFuncAttributeMaxDynamicSharedMemorySize, SM_64);
    cudaFuncSetAttribute(tgemm<64,256,0,0,1,0,1,0,1,0,0>,  cudaFuncAttributeMaxDynamicSharedMemorySize, SM_64);

    const dim3 tblk(32, 8);
    const float scale = 0.03125f;  // 1024^-0.5

    // weight prep
    pack_wkv<<<(C_ * 2 * D_) / 256, 256>>>(Wk, Wv, wkv);
    round_copy<<<(D_ * D_)   / 256, 256>>>(Wq, wq);
    round_copy<<<(D_ * MLP_) / 256, 256>>>(W1, w1);
    round_copy<<<(MLP_ * D_) / 256, 256>>>(W2, w2);

    // x [B,C,L] -> xn [B,L,C], then LN over C (rounded output)
    transpose_k<<<dim3(L_ / 32, C_ / 32, B_), tblk>>>(x, xn, C_, L_);
    ln1024<<<B_ * L_, 256>>>(xn, ln_in_g, ln_in_b, xn);

    // [K|V] = xn @ wkv : [32768,1024]x[1024,2048], one pass over xn
    tgemm<128,256,0,0,0,0,0,1,1,0,0><<<dim3(2 * D_ / 256, (B_ * L_) / 128, 1), 256, SM_KV>>>(
        xn, wkv, nullptr, nullptr, kv, B_ * L_, 2 * D_, C_, C_, 2 * D_, 2 * D_, 0, 0, 0, 1.f);

    bcast_tmpl<<<(B_ * N_ * D_) / 256, 256>>>(tinit, tmpl);

    for (int it = 0; it < TIT_; ++it) {
        // t = LN(t_prev); q = (t@Wq)*scale
        ln1024<<<B_ * N_, 256>>>(tmpl, ln_t_g, ln_t_b, tb);
        tgemm<64,256,0,0,0,0,0,1,1,0,0><<<dim3(D_ / 256, (B_ * N_) / 64, 1), 128, SM_64>>>(
            tb, wq, nullptr, nullptr, qb, B_ * N_, D_, D_, D_, D_, D_, 0, 0, 0, scale);

        zero_scratch<<<(B_ * N_ * D_) / 1024, 256>>>(upd, cs);

        // fused: logits = K@q^T, softmax over N (+1e-8), colsum atomics
        tgemm<64,256,0,1,0,0,0,0,1,0,1><<<dim3(1, L_ / 64, B_), 128, SM_LOG>>>(
            kv, qb, cs, nullptr, attn, L_, N_, D_, 2 * D_, D_, N_,
            (long long)L_ * 2 * D_, (long long)N_ * D_, (long long)L_ * N_, 1.f);

        // upd = attn_raw^T @ V, split-K x4 atomic partials
        tgemm<128,256,1,0,0,0,0,0,4,1,0><<<dim3(D_ / 256, N_ / 128, B_ * 4), 256, SM_UPD>>>(
            attn, kv + D_, nullptr, nullptr, upd, N_, D_, L_, N_, 2 * D_, D_,
            (long long)L_ * N_, (long long)L_ * 2 * D_, (long long)N_ * D_, 1.f);

        // templates += upd / colsum  (exact fold of the L-renorm)
        apply_update<<<(B_ * N_ * D_) / 1024, 256>>>(tmpl, upd, cs);

        // m = LN(templates); templates += relu(m@W1+b1)@W2 + b2
        ln1024<<<B_ * N_, 256>>>(tmpl, ln_m_g, ln_m_b, mb);
        tgemm<64,256,0,0,1,1,0,1,1,0,0><<<dim3(MLP_ / 256, (B_ * N_) / 64, 1), 128, SM_64>>>(
            mb, w1, b1, nullptr, hb, B_ * N_, MLP_, D_, D_, MLP_, MLP_, 0, 0, 0, 1.f);
        tgemm<64,256,0,0,1,0,1,0,1,0,0><<<dim3(D_ / 256, (B_ * N_) / 64, 1), 128, SM_64>>>(
            hb, w2, b2, tmpl, tmpl, B_ * N_, D_, MLP_, MLP_, D_, D_, 0, 0, 0, 1.f);
    }

    // final attn renorm (only needed for the output tensor)
    renorm_div<<<B_ * L_, 256>>>(attn, cs);

    // out_templates [B,D,N]; out_attn [B,N,H,W]
    transpose_k<<<dim3(D_ / 32, N_ / 32, B_), tblk>>>(tmpl, out, N_, D_);
    transpose_k<<<dim3(N_ / 32, L_ / 32, B_), tblk>>>(
        attn, out + (size_t)B_ * D_ * N_, L_, N_);
}

// round 8
// speedup vs baseline: 1.7452x; 1.7452x over previous
#include <cuda_runtime.h>
#include <cstddef>

#define B_    8
#define L_    4096
#define C_    1024
#define D_    1024
#define N_    256
#define MLP_  512
#define TIT_  6

// ---------------- scratch (device globals; no allocation allowed) ----------
__device__ float g_xn  [(size_t)B_ * L_ * C_];
__device__ float g_kv  [(size_t)B_ * L_ * 2 * D_];   // [l, 0:1024]=K, [l,1024:2048]=V
__device__ float g_attn[(size_t)B_ * L_ * N_];
__device__ float g_tmpl[B_ * N_ * D_];
__device__ float g_t   [B_ * N_ * D_];
__device__ float g_q   [B_ * N_ * D_];
__device__ float g_m   [B_ * N_ * D_];
__device__ float g_h   [B_ * N_ * MLP_];
__device__ float g_upd [B_ * N_ * D_];
__device__ float g_cs  [B_ * N_];
__device__ float g_wq  [D_ * D_];
__device__ float g_wkv [C_ * 2 * D_];
__device__ float g_w1  [D_ * MLP_];
__device__ float g_w2  [MLP_ * D_];

// ---------------- tf32 helpers ---------------------------------------------
__device__ __forceinline__ float to_tf32(float x) {
    unsigned u;
    asm("cvt.rna.tf32.f32 %0, %1;" : "=r"(u) : "f"(x));
    return __uint_as_float(u);
}

__device__ __forceinline__ void cp16(void* smem_dst, const void* gmem_src) {
    unsigned s = (unsigned)__cvta_generic_to_shared(smem_dst);
    asm volatile("cp.async.cg.shared.global [%0], [%1], 16;\n"
                 :: "r"(s), "l"(gmem_src));
}

// ---------------- tf32 tensor-core GEMM, cp.async double-buffered -----------
// C[M,N] = alpha*op(A)op(B) (+bias)(relu)(+resid) | atomic partials | fused softmax
// TA==0: A is [M,K].  TA==1: A is [K,M].   TB==0: B is [K,N].  TB==1: B is [N,K].
// CTA tile BM x BN x 32; warp tile fixed 64x64 (m16n8k8); threads = BM/64*BN/64*32.
// NOTE: 256-thread configs MUST get minblocks=1 (reg cap 256) — minblocks=2
// caps at 128 regs and spills the 128-reg accumulator array (R7 regression).
template<int BM, int BN, int TA, int TB, int BIAS, int RELU, int RESID, int CVT,
         int SPLITK, int ATOMIC, int SMAX>
__global__ void __launch_bounds__((BM / 64) * (BN / 64) * 32,
                                  ((BM / 64) * (BN / 64) * 32 == 128) ? 2 : 1)
tgemm(
    const float* __restrict__ A, const float* __restrict__ Bm,
    const float* __restrict__ bias, const float* __restrict__ Rm,
    float* __restrict__ Cm,
    int M, int N, int K, int lda, int ldb, int ldc,
    long long sA, long long sB, long long sC, float alpha)
{
    constexpr int WM = BM / 64, WN = BN / 64;
    constexpr int THREADS = WM * WN * 32;
    constexpr int AST = (TA == 0) ? BM * 36 : 32 * (BM + 8);
    constexpr int BST = (TB == 0) ? 32 * (BN + 8) : BN * 36;
    constexpr int NA = BM * 8 / THREADS;
    constexpr int NB = BN * 8 / THREADS;
    extern __shared__ float sm[];
    float* As = sm;
    float* Bs = sm + 2 * AST;

    int bz = blockIdx.z, batch = bz, koff = 0;
    if (SPLITK > 1) { batch = bz / SPLITK; koff = (bz % SPLITK) * (K / SPLITK); }
    A  += (size_t)batch * sA + (TA ? (size_t)koff * lda : (size_t)koff);
    Bm += (size_t)batch * sB + (TB ? (size_t)koff : (size_t)koff * ldb);
    Cm += (size_t)batch * sC;
    const float* Rp = RESID ? (Rm + (size_t)batch * sC) : nullptr;

    const int m0 = blockIdx.y * BM, n0 = blockIdx.x * BN;
    const int tid = threadIdx.x, lane = tid & 31, wid = tid >> 5;
    const int wm = (wid % WM) * 64, wn = (wid / WM) * 64;
    const int g = lane >> 2, tig = lane & 3;

    float acc[4][8][4] = {};

    auto load_stage = [&](int k0, int s) {
        float* Ad = As + s * AST;
        float* Bd = Bs + s * BST;
#pragma unroll
        for (int i = 0; i < NA; i++) {
            const int idx = tid + i * THREADS;
            if (TA == 0) {
                const int row = idx >> 3, kc = (idx & 7) * 4;
                cp16(Ad + row * 36 + kc, A + (size_t)(m0 + row) * lda + k0 + kc);
            } else {
                const int kk = idx / (BM / 4), mc = (idx % (BM / 4)) * 4;
                cp16(Ad + kk * (BM + 8) + mc, A + (size_t)(k0 + kk) * lda + m0 + mc);
            }
        }
#pragma unroll
        for (int i = 0; i < NB; i++) {
            const int idx = tid + i * THREADS;
            if (TB == 0) {
                const int kk = idx / (BN / 4), nc = (idx % (BN / 4)) * 4;
                cp16(Bd + kk * (BN + 8) + nc, Bm + (size_t)(k0 + kk) * ldb + n0 + nc);
            } else {
                const int row = idx >> 3, kc = (idx & 7) * 4;
                cp16(Bd + row * 36 + kc, Bm + (size_t)(n0 + row) * ldb + k0 + kc);
            }
        }
        asm volatile("cp.async.commit_group;\n");
    };

    auto compute = [&](int s) {
        const float* Ab = As + s * AST;
        const float* Bb = Bs + s * BST;
#pragma unroll
        for (int ks = 0; ks < 4; ks++) {
            const int kb = ks * 8;
            unsigned a[4][4], b[8][2];
#pragma unroll
            for (int mt = 0; mt < 4; mt++) {
                const int row = wm + mt * 16 + g;
                if (TA == 0) {
                    const int base = row * 36 + kb + tig;
                    a[mt][0] = __float_as_uint(Ab[base]);
                    a[mt][1] = __float_as_uint(Ab[base + 8 * 36]);
                    a[mt][2] = __float_as_uint(Ab[base + 4]);
                    a[mt][3] = __float_as_uint(Ab[base + 8 * 36 + 4]);
                } else {
                    const int base = (kb + tig) * (BM + 8) + row;
                    a[mt][0] = __float_as_uint(Ab[base]);
                    a[mt][1] = __float_as_uint(Ab[base + 8]);
                    a[mt][2] = __float_as_uint(Ab[base + 4 * (BM + 8)]);
                    a[mt][3] = __float_as_uint(Ab[base + 4 * (BM + 8) + 8]);
                }
            }
#pragma unroll
            for (int nt = 0; nt < 8; nt++) {
                const int col = wn + nt * 8 + g;
                if (TB == 0) {
                    b[nt][0] = __float_as_uint(Bb[(kb + tig) * (BN + 8) + col]);
                    b[nt][1] = __float_as_uint(Bb[(kb + tig + 4) * (BN + 8) + col]);
                } else {
                    b[nt][0] = __float_as_uint(Bb[col * 36 + kb + tig]);
                    b[nt][1] = __float_as_uint(Bb[col * 36 + kb + tig + 4]);
                }
            }
#pragma unroll
            for (int mt = 0; mt < 4; mt++)
#pragma unroll
                for (int nt = 0; nt < 8; nt++)
                    asm volatile(
                        "mma.sync.aligned.m16n8k8.row.col.f32.tf32.tf32.f32 "
                        "{%0,%1,%2,%3}, {%4,%5,%6,%7}, {%8,%9}, {%0,%1,%2,%3};"
                        : "+f"(acc[mt][nt][0]), "+f"(acc[mt][nt][1]),
                          "+f"(acc[mt][nt][2]), "+f"(acc[mt][nt][3])
                        : "r"(a[mt][0]), "r"(a[mt][1]), "r"(a[mt][2]), "r"(a[mt][3]),
                          "r"(b[nt][0]), "r"(b[nt][1]));
        }
    };

    load_stage(0, 0);
    const int T = ((SPLITK > 1) ? K / SPLITK : K) >> 5;
    for (int t = 0; t < T; t++) {
        asm volatile("cp.async.wait_group 0;\n");
        __syncthreads();
        if (t + 1 < T) load_stage((t + 1) << 5, (t + 1) & 1);
        compute(t & 1);
    }

    if (SMAX) {
        // BM=64, WM=1: each warp owns all 64 rows x its 64 cols. Full row in CTA.
        float* red = sm;                        // [64][WN]
        float fmx[4][2], fsm[4][2];
        __syncthreads();
        // ---- row max ----
#pragma unroll
        for (int mt = 0; mt < 4; mt++) {
            float h0 = -1e30f, h1 = -1e30f;
#pragma unroll
            for (int nt = 0; nt < 8; nt++) {
                h0 = fmaxf(h0, fmaxf(acc[mt][nt][0], acc[mt][nt][1]));
                h1 = fmaxf(h1, fmaxf(acc[mt][nt][2], acc[mt][nt][3]));
            }
            h0 = fmaxf(h0, __shfl_xor_sync(0xffffffffu, h0, 1));
            h0 = fmaxf(h0, __shfl_xor_sync(0xffffffffu, h0, 2));
            h1 = fmaxf(h1, __shfl_xor_sync(0xffffffffu, h1, 1));
            h1 = fmaxf(h1, __shfl_xor_sync(0xffffffffu, h1, 2));
            fmx[mt][0] = h0; fmx[mt][1] = h1;
        }
        if (tig == 0)
#pragma unroll
            for (int mt = 0; mt < 4; mt++) {
                red[(mt * 16 + g) * WN + wid] = fmx[mt][0];
                red[(mt * 16 + g + 8) * WN + wid] = fmx[mt][1];
            }
        __syncthreads();
#pragma unroll
        for (int mt = 0; mt < 4; mt++) {
            float h0 = -1e30f, h1 = -1e30f;
#pragma unroll
            for (int w = 0; w < WN; w++) {
                h0 = fmaxf(h0, red[(mt * 16 + g) * WN + w]);
                h1 = fmaxf(h1, red[(mt * 16 + g + 8) * WN + w]);
            }
            fmx[mt][0] = h0; fmx[mt][1] = h1;
        }
        __syncthreads();
        // ---- exp + row sum ----
#pragma unroll
        for (int mt = 0; mt < 4; mt++) {
            float s0 = 0.f, s1 = 0.f;
#pragma unroll
            for (int nt = 0; nt < 8; nt++) {
                acc[mt][nt][0] = __expf(acc[mt][nt][0] - fmx[mt][0]);
                acc[mt][nt][1] = __expf(acc[mt][nt][1] - fmx[mt][0]);
                acc[mt][nt][2] = __expf(acc[mt][nt][2] - fmx[mt][1]);
                acc[mt][nt][3] = __expf(acc[mt][nt][3] - fmx[mt][1]);
                s0 += acc[mt][nt][0] + acc[mt][nt][1];
                s1 += acc[mt][nt][2] + acc[mt][nt][3];
            }
            s0 += __shfl_xor_sync(0xffffffffu, s0, 1);
            s0 += __shfl_xor_sync(0xffffffffu, s0, 2);
            s1 += __shfl_xor_sync(0xffffffffu, s1, 1);
            s1 += __shfl_xor_sync(0xffffffffu, s1, 2);
            fsm[mt][0] = s0; fsm[mt][1] = s1;
        }
        if (tig == 0)
#pragma unroll
            for (int mt = 0; mt < 4; mt++) {
                red[(mt * 16 + g) * WN + wid] = fsm[mt][0];
                red[(mt * 16 + g + 8) * WN + wid] = fsm[mt][1];
            }
        __syncthreads();
#pragma unroll
        for (int mt = 0; mt < 4; mt++) {
            float s0 = 0.f, s1 = 0.f;
#pragma unroll
            for (int w = 0; w < WN; w++) {
                s0 += red[(mt * 16 + g) * WN + w];
                s1 += red[(mt * 16 + g + 8) * WN + w];
            }
            fsm[mt][0] = 1.f / s0; fsm[mt][1] = 1.f / s1;
        }
        // ---- a = e/sum + 1e-8: store + column partial sums ----
        float csum[8][2];
#pragma unroll
        for (int nt = 0; nt < 8; nt++) { csum[nt][0] = 0.f; csum[nt][1] = 0.f; }
#pragma unroll
        for (int mt = 0; mt < 4; mt++) {
            const int r0 = m0 + mt * 16 + g, r1 = r0 + 8;
#pragma unroll
            for (int nt = 0; nt < 8; nt++) {
                const int c = n0 + wn + nt * 8 + tig * 2;
                const float a0 = acc[mt][nt][0] * fsm[mt][0] + 1e-8f;
                const float a1 = acc[mt][nt][1] * fsm[mt][0] + 1e-8f;
                const float a2 = acc[mt][nt][2] * fsm[mt][1] + 1e-8f;
                const float a3 = acc[mt][nt][3] * fsm[mt][1] + 1e-8f;
                float2 o0; o0.x = a0; o0.y = a1;
                float2 o1; o1.x = a2; o1.y = a3;
                *(float2*)(Cm + (size_t)r0 * ldc + c) = o0;
                *(float2*)(Cm + (size_t)r1 * ldc + c) = o1;
                csum[nt][0] += a0 + a2;
                csum[nt][1] += a1 + a3;
            }
        }
        float* csp = (float*)bias + batch * N_;
#pragma unroll
        for (int nt = 0; nt < 8; nt++) {
            float s0 = csum[nt][0], s1 = csum[nt][1];
            s0 += __shfl_xor_sync(0xffffffffu, s0, 4);
            s0 += __shfl_xor_sync(0xffffffffu, s0, 8);
            s0 += __shfl_xor_sync(0xffffffffu, s0, 16);
            s1 += __shfl_xor_sync(0xffffffffu, s1, 4);
            s1 += __shfl_xor_sync(0xffffffffu, s1, 8);
            s1 += __shfl_xor_sync(0xffffffffu, s1, 16);
            if (lane < 4) {
                const int c = n0 + wn + nt * 8 + lane * 2;
                atomicAdd(csp + c, s0);
                atomicAdd(csp + c + 1, s1);
            }
        }
        return;
    }

#pragma unroll
    for (int mt = 0; mt < 4; mt++) {
        const int r0 = m0 + wm + mt * 16 + g, r1 = r0 + 8;
#pragma unroll
        for (int nt = 0; nt < 8; nt++) {
            const int c = n0 + wn + nt * 8 + tig * 2;
            float v0 = acc[mt][nt][0] * alpha, v1 = acc[mt][nt][1] * alpha;
            float v2 = acc[mt][nt][2] * alpha, v3 = acc[mt][nt][3] * alpha;
            if (ATOMIC) {
                atomicAdd(Cm + (size_t)r0 * ldc + c,     v0);
                atomicAdd(Cm + (size_t)r0 * ldc + c + 1, v1);
                atomicAdd(Cm + (size_t)r1 * ldc + c,     v2);
                atomicAdd(Cm + (size_t)r1 * ldc + c + 1, v3);
                continue;
            }
            if (BIAS) {
                const float bx = bias[c], by = bias[c + 1];
                v0 += bx; v1 += by; v2 += bx; v3 += by;
            }
            if (RELU) {
                v0 = fmaxf(v0, 0.f); v1 = fmaxf(v1, 0.f);
                v2 = fmaxf(v2, 0.f); v3 = fmaxf(v3, 0.f);
            }
            if (RESID) {
                const float2 p = *(const float2*)(Rp + (size_t)r0 * ldc + c);
                const float2 q = *(const float2*)(Rp + (size_t)r1 * ldc + c);
                v0 += p.x; v1 += p.y; v2 += q.x; v3 += q.y;
            }
            if (CVT) {
                v0 = to_tf32(v0); v1 = to_tf32(v1);
                v2 = to_tf32(v2); v3 = to_tf32(v3);
            }
            float2 o0; o0.x = v0; o0.y = v1;
            float2 o1; o1.x = v2; o1.y = v3;
            *(float2*)(Cm + (size_t)r0 * ldc + c) = o0;
            *(float2*)(Cm + (size_t)r1 * ldc + c) = o1;
        }
    }
}

// ---------------- LayerNorm over 1024-wide rows (tf32-rounded output) -------
__global__ void __launch_bounds__(256) ln1024(
    const float* __restrict__ in, const float* __restrict__ g,
    const float* __restrict__ b, float* __restrict__ out)
{
    __shared__ float sh[8];
    __shared__ float s_mean, s_rstd;
    const size_t row = blockIdx.x;
    const int t = threadIdx.x;
    const float4 v = ((const float4*)(in + row * 1024))[t];

    float s = v.x + v.y + v.z + v.w;
#pragma unroll
    for (int o = 16; o; o >>= 1) s += __shfl_xor_sync(0xffffffffu, s, o);
    if ((t & 31) == 0) sh[t >> 5] = s;
    __syncthreads();
    if (t == 0) {
        float tt = 0.f;
#pragma unroll
        for (int i = 0; i < 8; i++) tt += sh[i];
        s_mean = tt * (1.f / 1024.f);
    }
    __syncthreads();
    const float mean = s_mean;
    const float dx = v.x - mean, dy = v.y - mean, dz = v.z - mean, dw = v.w - mean;

    float q = dx * dx + dy * dy + dz * dz + dw * dw;
#pragma unroll
    for (int o = 16; o; o >>= 1) q += __shfl_xor_sync(0xffffffffu, q, o);
    __syncthreads();
    if ((t & 31) == 0) sh[t >> 5] = q;
    __syncthreads();
    if (t == 0) {
        float tt = 0.f;
#pragma unroll
        for (int i = 0; i < 8; i++) tt += sh[i];
        s_rstd = rsqrtf(tt * (1.f / 1024.f) + 1e-5f);
    }
    __syncthreads();
    const float rstd = s_rstd;

    const float4 gv = ((const float4*)g)[t];
    const float4 bv = ((const float4*)b)[t];
    float4 o;
    o.x = to_tf32(dx * rstd * gv.x + bv.x);
    o.y = to_tf32(dy * rstd * gv.y + bv.y);
    o.z = to_tf32(dz * rstd * gv.z + bv.z);
    o.w = to_tf32(dw * rstd * gv.w + bv.w);
    ((float4*)(out + row * 1024))[t] = o;
}

__global__ void renorm_div(float* __restrict__ attn, const float* __restrict__ colsum)
{
    const size_t row = blockIdx.x;
    const int n = threadIdx.x;
    attn[row * 256 + n] /= colsum[(row >> 12) * 256 + n];
}

// zero colsum [B*N] and upd [B*N*D] (float4 stores)
__global__ void zero_scratch(float* __restrict__ upd, float* __restrict__ cs)
{
    const size_t i = (size_t)blockIdx.x * 256 + threadIdx.x;
    ((float4*)upd)[i] = make_float4(0.f, 0.f, 0.f, 0.f);
    if (i < B_ * N_) cs[i] = 0.f;
}

// tmpl += upd / colsum[row]  (the folded L-renorm)
__global__ void apply_update(float* __restrict__ tmpl, const float* __restrict__ upd,
                             const float* __restrict__ cs)
{
    const size_t i = (size_t)blockIdx.x * 256 + threadIdx.x;
    const int row = (int)(i / (D_ / 4));
    const float s = 1.f / cs[row];
    const float4 u = ((const float4*)upd)[i];
    float4 t = ((float4*)tmpl)[i];
    t.x += u.x * s; t.y += u.y * s; t.z += u.z * s; t.w += u.w * s;
    ((float4*)tmpl)[i] = t;
}

// ---------------- tiled transpose: per batch [R,Cc] -> [Cc,R] --------------
__global__ void transpose_k(const float* __restrict__ in, float* __restrict__ out,
                            int R, int Cc)
{
    __shared__ float tile[32][33];
    const size_t base = (size_t)blockIdx.z * R * Cc;
    const int c0 = blockIdx.x * 32, r0 = blockIdx.y * 32;
#pragma unroll
    for (int i = threadIdx.y; i < 32; i += 8)
        tile[i][threadIdx.x] = in[base + (size_t)(r0 + i) * Cc + c0 + threadIdx.x];
    __syncthreads();
#pragma unroll
    for (int i = threadIdx.y; i < 32; i += 8)
        out[base + (size_t)(c0 + i) * R + r0 + threadIdx.x] = tile[threadIdx.x][i];
}

__global__ void bcast_tmpl(const float* __restrict__ tinit, float* __restrict__ tmpl)
{
    const size_t i = (size_t)blockIdx.x * 256 + threadIdx.x;
    tmpl[i] = tinit[i & ((size_t)N_ * D_ - 1)];
}

__global__ void round_copy(const float* __restrict__ in, float* __restrict__ out)
{
    const size_t i = (size_t)blockIdx.x * 256 + threadIdx.x;
    out[i] = to_tf32(in[i]);
}

// wkv[k][j] = tf32(j<1024 ? Wk[k][j] : Wv[k][j-1024])
__global__ void pack_wkv(const float* __restrict__ Wk, const float* __restrict__ Wv,
                         float* __restrict__ wkv)
{
    const size_t i = (size_t)blockIdx.x * 256 + threadIdx.x;
    const int k = (int)(i >> 11), j = (int)(i & 2047);
    const float v = (j < D_) ? Wk[k * D_ + j] : Wv[k * D_ + j - D_];
    wkv[i] = to_tf32(v);
}

// ---------------- host orchestration ---------------------------------------
extern "C" void kernel_launch(void* const* d_in, const int* in_sizes, int n_in,
                              void* d_out, int out_size)
{
    const float* x       = (const float*)d_in[0];
    const float* tinit   = (const float*)d_in[1];
    const float* Wq      = (const float*)d_in[2];
    const float* Wk      = (const float*)d_in[3];
    const float* Wv      = (const float*)d_in[4];
    const float* ln_in_g = (const float*)d_in[5];
    const float* ln_in_b = (const float*)d_in[6];
    const float* ln_t_g  = (const float*)d_in[7];
    const float* ln_t_b  = (const float*)d_in[8];
    const float* ln_m_g  = (const float*)d_in[9];
    const float* ln_m_b  = (const float*)d_in[10];
    const float* W1      = (const float*)d_in[11];
    const float* b1      = (const float*)d_in[12];
    const float* W2      = (const float*)d_in[13];
    const float* b2      = (const float*)d_in[14];
    float* out = (float*)d_out;

    float *xn, *kv, *attn, *tmpl, *tb, *qb, *mb, *hb, *upd, *cs;
    float *wq, *wkv, *w1, *w2;
    cudaGetSymbolAddress((void**)&xn,   g_xn);
    cudaGetSymbolAddress((void**)&kv,   g_kv);
    cudaGetSymbolAddress((void**)&attn, g_attn);
    cudaGetSymbolAddress((void**)&tmpl, g_tmpl);
    cudaGetSymbolAddress((void**)&tb,   g_t);
    cudaGetSymbolAddress((void**)&qb,   g_q);
    cudaGetSymbolAddress((void**)&mb,   g_m);
    cudaGetSymbolAddress((void**)&hb,   g_h);
    cudaGetSymbolAddress((void**)&upd,  g_upd);
    cudaGetSymbolAddress((void**)&cs,   g_cs);
    cudaGetSymbolAddress((void**)&wq,   g_wq);
    cudaGetSymbolAddress((void**)&wkv,  g_wkv);
    cudaGetSymbolAddress((void**)&w1,   g_w1);
    cudaGetSymbolAddress((void**)&w2,   g_w2);

    // smem sizes: 2*(AST+BST)*4 bytes
    const int SM_KV  = 2 * (128 * 36 + 32 * 264) * 4;   // 104448  BM128 BN256 TA0 TB0
    const int SM_LOG = 2 * (64 * 36 + 256 * 36) * 4;    // 92160   BM64  BN256 TA0 TB1
    const int SM_UPD = 2 * (32 * 136 + 32 * 264) * 4;   // 102400  BM128 BN256 TA1 TB0
    const int SM_64  = 2 * (64 * 36 + 32 * 264) * 4;    // 86016   BM64  BN256 TA0 TB0

    cudaFuncSetAttribute(tgemm<128,256,0,0,0,0,0,1,1,0,0>, cudaFuncAttributeMaxDynamicSharedMemorySize, SM_KV);
    cudaFuncSetAttribute(tgemm<64,256,0,1,0,0,0,0,1,0,1>,  cudaFuncAttributeMaxDynamicSharedMemorySize, SM_LOG);
    cudaFuncSetAttribute(tgemm<128,256,1,0,0,0,0,0,8,1,0>, cudaFuncAttributeMaxDynamicSharedMemorySize, SM_UPD);
    cudaFuncSetAttribute(tgemm<64,256,0,0,0,0,0,1,1,0,0>,  cudaFuncAttributeMaxDynamicSharedMemorySize, SM_64);
    cudaFuncSetAttribute(tgemm<64,256,0,0,1,1,0,1,1,0,0>,  cudaFuncAttributeMaxDynamicSharedMemorySize, SM_64);
    cudaFuncSetAttribute(tgemm<64,256,0,0,1,0,1,0,1,0,0>,  cudaFuncAttributeMaxDynamicSharedMemorySize, SM_64);

    const dim3 tblk(32, 8);
    const float scale = 0.03125f;  // 1024^-0.5

    // weight prep
    pack_wkv<<<(C_ * 2 * D_) / 256, 256>>>(Wk, Wv, wkv);
    round_copy<<<(D_ * D_)   / 256, 256>>>(Wq, wq);
    round_copy<<<(D_ * MLP_) / 256, 256>>>(W1, w1);
    round_copy<<<(MLP_ * D_) / 256, 256>>>(W2, w2);

    // x [B,C,L] -> xn [B,L,C], then LN over C (rounded output)
    transpose_k<<<dim3(L_ / 32, C_ / 32, B_), tblk>>>(x, xn, C_, L_);
    ln1024<<<B_ * L_, 256>>>(xn, ln_in_g, ln_in_b, xn);

    // [K|V] = xn @ wkv : [32768,1024]x[1024,2048], one pass over xn
    tgemm<128,256,0,0,0,0,0,1,1,0,0><<<dim3(2 * D_ / 256, (B_ * L_) / 128, 1), 256, SM_KV>>>(
        xn, wkv, nullptr, nullptr, kv, B_ * L_, 2 * D_, C_, C_, 2 * D_, 2 * D_, 0, 0, 0, 1.f);

    bcast_tmpl<<<(B_ * N_ * D_) / 256, 256>>>(tinit, tmpl);

    for (int it = 0; it < TIT_; ++it) {
        // t = LN(t_prev); q = (t@Wq)*scale
        ln1024<<<B_ * N_, 256>>>(tmpl, ln_t_g, ln_t_b, tb);
        tgemm<64,256,0,0,0,0,0,1,1,0,0><<<dim3(D_ / 256, (B_ * N_) / 64, 1), 128, SM_64>>>(
            tb, wq, nullptr, nullptr, qb, B_ * N_, D_, D_, D_, D_, D_, 0, 0, 0, scale);

        zero_scratch<<<(B_ * N_ * D_) / 1024, 256>>>(upd, cs);

        // fused: logits = K@q^T, softmax over N (+1e-8), colsum atomics
        tgemm<64,256,0,1,0,0,0,0,1,0,1><<<dim3(1, L_ / 64, B_), 128, SM_LOG>>>(
            kv, qb, cs, nullptr, attn, L_, N_, D_, 2 * D_, D_, N_,
            (long long)L_ * 2 * D_, (long long)N_ * D_, (long long)L_ * N_, 1.f);

        // upd = attn_raw^T @ V, split-K x8 atomic partials
        tgemm<128,256,1,0,0,0,0,0,8,1,0><<<dim3(D_ / 256, N_ / 128, B_ * 8), 256, SM_UPD>>>(
            attn, kv + D_, nullptr, nullptr, upd, N_, D_, L_, N_, 2 * D_, D_,
            (long long)L_ * N_, (long long)L_ * 2 * D_, (long long)N_ * D_, 1.f);

        // templates += upd / colsum  (exact fold of the L-renorm)
        apply_update<<<(B_ * N_ * D_) / 1024, 256>>>(tmpl, upd, cs);

        // m = LN(templates); templates += relu(m@W1+b1)@W2 + b2
        ln1024<<<B_ * N_, 256>>>(tmpl, ln_m_g, ln_m_b, mb);
        tgemm<64,256,0,0,1,1,0,1,1,0,0><<<dim3(MLP_ / 256, (B_ * N_) / 64, 1), 128, SM_64>>>(
            mb, w1, b1, nullptr, hb, B_ * N_, MLP_, D_, D_, MLP_, MLP_, 0, 0, 0, 1.f);
        tgemm<64,256,0,0,1,0,1,0,1,0,0><<<dim3(D_ / 256, (B_ * N_) / 64, 1), 128, SM_64>>>(
            hb, w2, b2, tmpl, tmpl, B_ * N_, D_, MLP_, MLP_, D_, D_, 0, 0, 0, 1.f);
    }

    // final attn renorm (only needed for the output tensor)
    renorm_div<<<B_ * L_, 256>>>(attn, cs);

    // out_templates [B,D,N]; out_attn [B,N,H,W]
    transpose_k<<<dim3(D_ / 32, N_ / 32, B_), tblk>>>(tmpl, out, N_, D_);
    transpose_k<<<dim3(N_ / 32, L_ / 32, B_), tblk>>>(
        attn, out + (size_t)B_ * D_ * N_, L_, N_);
}

// round 12
// speedup vs baseline: 2.4060x; 1.3787x over previous
#include <cuda_runtime.h>
#include <cuda_fp16.h>
#include <cstddef>

#define B_    8
#define L_    4096
#define C_    1024
#define D_    1024
#define N_    256
#define MLP_  512
#define TIT_  6

// ---------------- scratch (device globals; no allocation allowed) ----------
__device__ float  g_xn  [(size_t)B_ * L_ * C_];
__device__ __half g_xn16[(size_t)B_ * L_ * C_];
__device__ __half g_kv16[(size_t)B_ * L_ * 2 * D_];  // [l][0:1024]=K, [l][1024:2048]=V
__device__ __half g_vT  [(size_t)B_ * D_ * L_];      // V transposed [d][l]
__device__ __half g_aT  [(size_t)B_ * N_ * L_];      // attn^T [n][l], fp16
__device__ float  g_tmpl[B_ * N_ * D_];
__device__ float  g_upd [B_ * N_ * D_];
__device__ float  g_cs  [B_ * N_];
__device__ __half g_t16 [B_ * N_ * D_];
__device__ __half g_q16 [B_ * N_ * D_];
__device__ __half g_m16 [B_ * N_ * D_];
__device__ __half g_h16 [B_ * N_ * MLP_];
__device__ __half g_wqT [D_ * D_];
__device__ __half g_wkvT[2 * D_ * C_];
__device__ __half g_w1T [MLP_ * D_];
__device__ __half g_w2T [D_ * MLP_];

__device__ __forceinline__ void cp16(void* smem_dst, const void* gmem_src) {
    unsigned s = (unsigned)__cvta_generic_to_shared(smem_dst);
    asm volatile("cp.async.cg.shared.global [%0], [%1], 16;\n"
                 :: "r"(s), "l"(gmem_src));
}

// ---------------- fp16 tensor-core GEMM, cp.async double-buffered -----------
// C[M,N] = alpha * A B^T (+bias)(relu)(+resid) | atomic partials | fused softmax
// A [M][K] and B [N][K], BOTH row-major k-contiguous fp16.
// CTA tile BM x BN x 32; warp tile 64x64 via mma.m16n8k16.f16; fp32 accum.
// smem pitch 40 halfs per 32-half row (conflict-free half2 fragment loads).
// SMAX (BM=64, BN=256=N_): softmax over N per row, writes attn^T fp16 [n][l]
// via smem-staged transpose; fp32 colsum atomics into cs.
template<int BM, int BN, int BIAS, int RELU, int RESID, int OUT16,
         int SPLITK, int ATOMIC, int SMAX>
__global__ void __launch_bounds__((BM / 64) * (BN / 64) * 32,
                                  ((BM / 64) * (BN / 64) * 32 == 128) ? 2 : 1)
hgemm(const __half* __restrict__ A, const __half* __restrict__ Bm,
      const float* __restrict__ bias, const float* __restrict__ Rm,
      void* __restrict__ Cv, float* __restrict__ cs,
      int M, int N, int K, int lda, int ldb, int ldc,
      long long sA, long long sB, long long sC, float alpha)
{
    constexpr int WM = BM / 64, WN = BN / 64;
    constexpr int THREADS = WM * WN * 32;
    constexpr int AST = BM * 40;             // halfs per stage
    constexpr int BST = BN * 40;
    constexpr int NA = BM * 4 / THREADS;     // cp16 per thread for A
    constexpr int NB = BN * 4 / THREADS;
    extern __shared__ __half sm16[];

    int bz = blockIdx.z, batch = bz, koff = 0;
    if (SPLITK > 1) { batch = bz / SPLITK; koff = (bz % SPLITK) * (K / SPLITK); }
    A  += (size_t)batch * sA + koff;
    Bm += (size_t)batch * sB + koff;
    const float* Rp = RESID ? (Rm + (size_t)batch * sC) : nullptr;

    const int m0 = blockIdx.y * BM, n0 = blockIdx.x * BN;
    const int tid = threadIdx.x, lane = tid & 31, wid = tid >> 5;
    const int wm = (wid % WM) * 64, wn = (wid / WM) * 64;
    const int g = lane >> 2, tig = lane & 3;

    float acc[4][8][4] = {};

    auto load_stage = [&](int k0, int s) {
        __half* Ad = sm16 + s * AST;
        __half* Bd = sm16 + 2 * AST + s * BST;
#pragma unroll
        for (int i = 0; i < NA; i++) {
            const int idx = tid + i * THREADS;
            const int row = idx >> 2, kc = (idx & 3) * 8;
            cp16(Ad + row * 40 + kc, A + (size_t)(m0 + row) * lda + k0 + kc);
        }
#pragma unroll
        for (int i = 0; i < NB; i++) {
            const int idx = tid + i * THREADS;
            const int row = idx >> 2, kc = (idx & 3) * 8;
            cp16(Bd + row * 40 + kc, Bm + (size_t)(n0 + row) * ldb + k0 + kc);
        }
        asm volatile("cp.async.commit_group;\n");
    };

    auto compute = [&](int s) {
        // half2 views; pitch = 20 half2 per row
        const unsigned* Ah = (const unsigned*)(sm16 + s * AST);
        const unsigned* Bh = (const unsigned*)(sm16 + 2 * AST + s * BST);
#pragma unroll
        for (int ks = 0; ks < 2; ks++) {           // two k16 steps per 32-tile
            const int kb = ks * 8;                 // half2 offset
            unsigned a[4][4], b[8][2];
#pragma unroll
            for (int mt = 0; mt < 4; mt++) {
                const int r = wm + mt * 16 + g;
                a[mt][0] = Ah[r * 20 + kb + tig];
                a[mt][1] = Ah[(r + 8) * 20 + kb + tig];
                a[mt][2] = Ah[r * 20 + kb + 4 + tig];
                a[mt][3] = Ah[(r + 8) * 20 + kb + 4 + tig];
            }
#pragma unroll
            for (int nt = 0; nt < 8; nt++) {
                const int c = wn + nt * 8 + g;
                b[nt][0] = Bh[c * 20 + kb + tig];
                b[nt][1] = Bh[c * 20 + kb + 4 + tig];
            }
#pragma unroll
            for (int mt = 0; mt < 4; mt++)
#pragma unroll
                for (int nt = 0; nt < 8; nt++)
                    asm volatile(
                        "mma.sync.aligned.m16n8k16.row.col.f32.f16.f16.f32 "
                        "{%0,%1,%2,%3}, {%4,%5,%6,%7}, {%8,%9}, {%0,%1,%2,%3};"
                        : "+f"(acc[mt][nt][0]), "+f"(acc[mt][nt][1]),
                          "+f"(acc[mt][nt][2]), "+f"(acc[mt][nt][3])
                        : "r"(a[mt][0]), "r"(a[mt][1]), "r"(a[mt][2]), "r"(a[mt][3]),
                          "r"(b[nt][0]), "r"(b[nt][1]));
        }
    };

    load_stage(0, 0);
    const int T = ((SPLITK > 1) ? K / SPLITK : K) >> 5;
    for (int t = 0; t < T; t++) {
        asm volatile("cp.async.wait_group 0;\n");
        __syncthreads();
        if (t + 1 < T) load_stage((t + 1) << 5, (t + 1) & 1);
        compute(t & 1);
    }

    if (SMAX) {
        // BM=64, BN=256: full softmax row per CTA; WM=1, wm=0.
        float* red = (float*)sm16;              // [64][WN]
        float fmx[4][2], fsm[4][2];
        __syncthreads();
        // ---- row max ----
#pragma unroll
        for (int mt = 0; mt < 4; mt++) {
            float h0 = -1e30f, h1 = -1e30f;
#pragma unroll
            for (int nt = 0; nt < 8; nt++) {
                h0 = fmaxf(h0, fmaxf(acc[mt][nt][0], acc[mt][nt][1]));
                h1 = fmaxf(h1, fmaxf(acc[mt][nt][2], acc[mt][nt][3]));
            }
            h0 = fmaxf(h0, __shfl_xor_sync(0xffffffffu, h0, 1));
            h0 = fmaxf(h0, __shfl_xor_sync(0xffffffffu, h0, 2));
            h1 = fmaxf(h1, __shfl_xor_sync(0xffffffffu, h1, 1));
            h1 = fmaxf(h1, __shfl_xor_sync(0xffffffffu, h1, 2));
            fmx[mt][0] = h0; fmx[mt][1] = h1;
        }
        if (tig == 0)
#pragma unroll
            for (int mt = 0; mt < 4; mt++) {
                red[(mt * 16 + g) * WN + wid] = fmx[mt][0];
                red[(mt * 16 + g + 8) * WN + wid] = fmx[mt][1];
            }
        __syncthreads();
#pragma unroll
        for (int mt = 0; mt < 4; mt++) {
            float h0 = -1e30f, h1 = -1e30f;
#pragma unroll
            for (int w = 0; w < WN; w++) {
                h0 = fmaxf(h0, red[(mt * 16 + g) * WN + w]);
                h1 = fmaxf(h1, red[(mt * 16 + g + 8) * WN + w]);
            }
            fmx[mt][0] = h0; fmx[mt][1] = h1;
        }
        __syncthreads();
        // ---- exp + row sum ----
#pragma unroll
        for (int mt = 0; mt < 4; mt++) {
            float s0 = 0.f, s1 = 0.f;
#pragma unroll
            for (int nt = 0; nt < 8; nt++) {
                acc[mt][nt][0] = __expf(acc[mt][nt][0] - fmx[mt][0]);
                acc[mt][nt][1] = __expf(acc[mt][nt][1] - fmx[mt][0]);
                acc[mt][nt][2] = __expf(acc[mt][nt][2] - fmx[mt][1]);
                acc[mt][nt][3] = __expf(acc[mt][nt][3] - fmx[mt][1]);
                s0 += acc[mt][nt][0] + acc[mt][nt][1];
                s1 += acc[mt][nt][2] + acc[mt][nt][3];
            }
            s0 += __shfl_xor_sync(0xffffffffu, s0, 1);
            s0 += __shfl_xor_sync(0xffffffffu, s0, 2);
            s1 += __shfl_xor_sync(0xffffffffu, s1, 1);
            s1 += __shfl_xor_sync(0xffffffffu, s1, 2);
            fsm[mt][0] = s0; fsm[mt][1] = s1;
        }
        if (tig == 0)
#pragma unroll
            for (int mt = 0; mt < 4; mt++) {
                red[(mt * 16 + g) * WN + wid] = fsm[mt][0];
                red[(mt * 16 + g + 8) * WN + wid] = fsm[mt][1];
            }
        __syncthreads();
#pragma unroll
        for (int mt = 0; mt < 4; mt++) {
            float s0 = 0.f, s1 = 0.f;
#pragma unroll
            for (int w = 0; w < WN; w++) {
                s0 += red[(mt * 16 + g) * WN + w];
                s1 += red[(mt * 16 + g + 8) * WN + w];
            }
            fsm[mt][0] = 1.f / s0; fsm[mt][1] = 1.f / s1;
        }
        __syncthreads();   // red region about to be reused as transpose tile
        // ---- normalize (+1e-8), stage transposed to smem, colsum fp32 ----
        __half* tt = sm16;                      // [256][80] halfs (pitch 80)
        float csum[8][2];
#pragma unroll
        for (int nt = 0; nt < 8; nt++) { csum[nt][0] = 0.f; csum[nt][1] = 0.f; }
#pragma unroll
        for (int mt = 0; mt < 4; mt++) {
            const int l0 = mt * 16 + g, l1 = l0 + 8;
#pragma unroll
            for (int nt = 0; nt < 8; nt++) {
                const int c = wn + nt * 8 + tig * 2;
                const float a0 = acc[mt][nt][0] * fsm[mt][0] + 1e-8f;
                const float a1 = acc[mt][nt][1] * fsm[mt][0] + 1e-8f;
                const float a2 = acc[mt][nt][2] * fsm[mt][1] + 1e-8f;
                const float a3 = acc[mt][nt][3] * fsm[mt][1] + 1e-8f;
                tt[c * 80 + l0]       = __float2half_rn(a0);
                tt[(c + 1) * 80 + l0] = __float2half_rn(a1);
                tt[c * 80 + l1]       = __float2half_rn(a2);
                tt[(c + 1) * 80 + l1] = __float2half_rn(a3);
                csum[nt][0] += a0 + a2;
                csum[nt][1] += a1 + a3;
            }
        }
        float* csp = cs + batch * N_;
#pragma unroll
        for (int nt = 0; nt < 8; nt++) {
            float s0 = csum[nt][0], s1 = csum[nt][1];
            s0 += __shfl_xor_sync(0xffffffffu, s0, 4);
            s0 += __shfl_xor_sync(0xffffffffu, s0, 8);
            s0 += __shfl_xor_sync(0xffffffffu, s0, 16);
            s1 += __shfl_xor_sync(0xffffffffu, s1, 4);
            s1 += __shfl_xor_sync(0xffffffffu, s1, 8);
            s1 += __shfl_xor_sync(0xffffffffu, s1, 16);
            if (lane < 4) {
                const int c = wn + nt * 8 + lane * 2;
                atomicAdd(csp + c, s0);
                atomicAdd(csp + c + 1, s1);
            }
        }
        __syncthreads();
        // ---- coalesced store: attn^T [n][l], 64 halfs per n-row ----
        __half* Ao = (__half*)Cv + (size_t)batch * sC;
        for (int n = tid; n < 256; n += THREADS) {
            const uint4* s4 = (const uint4*)(tt + n * 80);
            uint4* d4 = (uint4*)(Ao + (size_t)n * ldc + m0);
#pragma unroll
            for (int j = 0; j < 8; j++) d4[j] = s4[j];
        }
        return;
    }

    // ---------------- standard epilogues ----------------
    if (ATOMIC) {
        float* Cm = (float*)Cv + (size_t)batch * sC;
#pragma unroll
        for (int mt = 0; mt < 4; mt++) {
            const int r0 = m0 + wm + mt * 16 + g, r1 = r0 + 8;
#pragma unroll
            for (int nt = 0; nt < 8; nt++) {
                const int c = n0 + wn + nt * 8 + tig * 2;
                atomicAdd(Cm + (size_t)r0 * ldc + c,     acc[mt][nt][0]);
                atomicAdd(Cm + (size_t)r0 * ldc + c + 1, acc[mt][nt][1]);
                atomicAdd(Cm + (size_t)r1 * ldc + c,     acc[mt][nt][2]);
                atomicAdd(Cm + (size_t)r1 * ldc + c + 1, acc[mt][nt][3]);
            }
        }
        return;
    }
#pragma unroll
    for (int mt = 0; mt < 4; mt++) {
        const int r0 = m0 + wm + mt * 16 + g, r1 = r0 + 8;
#pragma unroll
        for (int nt = 0; nt < 8; nt++) {
            const int c = n0 + wn + nt * 8 + tig * 2;
            float v0 = acc[mt][nt][0] * alpha, v1 = acc[mt][nt][1] * alpha;
            float v2 = acc[mt][nt][2] * alpha, v3 = acc[mt][nt][3] * alpha;
            if (BIAS) {
                const float bx = bias[c], by = bias[c + 1];
                v0 += bx; v1 += by; v2 += bx; v3 += by;
            }
            if (RELU) {
                v0 = fmaxf(v0, 0.f); v1 = fmaxf(v1, 0.f);
                v2 = fmaxf(v2, 0.f); v3 = fmaxf(v3, 0.f);
            }
            if (RESID) {
                const float2 p = *(const float2*)(Rp + (size_t)r0 * ldc + c);
                const float2 q = *(const float2*)(Rp + (size_t)r1 * ldc + c);
                v0 += p.x; v1 += p.y; v2 += q.x; v3 += q.y;
            }
            if (OUT16) {
                __half* C16 = (__half*)Cv;
                *(__half2*)(C16 + (size_t)r0 * ldc + c) = __floats2half2_rn(v0, v1);
                *(__half2*)(C16 + (size_t)r1 * ldc + c) = __floats2half2_rn(v2, v3);
            } else {
                float* Cm = (float*)Cv + (size_t)batch * sC;
                float2 o0; o0.x = v0; o0.y = v1;
                float2 o1; o1.x = v2; o1.y = v3;
                *(float2*)(Cm + (size_t)r0 * ldc + c) = o0;
                *(float2*)(Cm + (size_t)r1 * ldc + c) = o1;
            }
        }
    }
}

// ---------------- LayerNorm over 1024-wide rows, fp16 output ----------------
__global__ void __launch_bounds__(256) ln1024h(
    const float* __restrict__ in, const float* __restrict__ g,
    const float* __restrict__ b, __half* __restrict__ out)
{
    __shared__ float sh[8];
    __shared__ float s_mean, s_rstd;
    const size_t row = blockIdx.x;
    const int t = threadIdx.x;
    const float4 v = ((const float4*)(in + row * 1024))[t];

    float s = v.x + v.y + v.z + v.w;
#pragma unroll
    for (int o = 16; o; o >>= 1) s += __shfl_xor_sync(0xffffffffu, s, o);
    if ((t & 31) == 0) sh[t >> 5] = s;
    __syncthreads();
    if (t == 0) {
        float tt = 0.f;
#pragma unroll
        for (int i = 0; i < 8; i++) tt += sh[i];
        s_mean = tt * (1.f / 1024.f);
    }
    __syncthreads();
    const float mean = s_mean;
    const float dx = v.x - mean, dy = v.y - mean, dz = v.z - mean, dw = v.w - mean;

    float q = dx * dx + dy * dy + dz * dz + dw * dw;
#pragma unroll
    for (int o = 16; o; o >>= 1) q += __shfl_xor_sync(0xffffffffu, q, o);
    __syncthreads();
    if ((t & 31) == 0) sh[t >> 5] = q;
    __syncthreads();
    if (t == 0) {
        float tt = 0.f;
#pragma unroll
        for (int i = 0; i < 8; i++) tt += sh[i];
        s_rstd = rsqrtf(tt * (1.f / 1024.f) + 1e-5f);
    }
    __syncthreads();
    const float rstd = s_rstd;

    const float4 gv = ((const float4*)g)[t];
    const float4 bv = ((const float4*)b)[t];
    __half2* oh = (__half2*)(out + row * 1024) + t * 2;
    oh[0] = __floats2half2_rn(dx * rstd * gv.x + bv.x, dy * rstd * gv.y + bv.y);
    oh[1] = __floats2half2_rn(dz * rstd * gv.z + bv.z, dw * rstd * gv.w + bv.w);
}

// zero colsum [B*N] and upd [B*N*D]
__global__ void zero_scratch(float* __restrict__ upd, float* __restrict__ cs)
{
    const size_t i = (size_t)blockIdx.x * 256 + threadIdx.x;
    ((float4*)upd)[i] = make_float4(0.f, 0.f, 0.f, 0.f);
    if (i < B_ * N_) cs[i] = 0.f;
}

// tmpl += upd / colsum[row]  (the folded L-renorm)
__global__ void apply_update(float* __restrict__ tmpl, const float* __restrict__ upd,
                             const float* __restrict__ cs)
{
    const size_t i = (size_t)blockIdx.x * 256 + threadIdx.x;
    const int row = (int)(i / (D_ / 4));
    const float s = 1.f / cs[row];
    const float4 u = ((const float4*)upd)[i];
    float4 t = ((float4*)tmpl)[i];
    t.x += u.x * s; t.y += u.y * s; t.z += u.z * s; t.w += u.w * s;
    ((float4*)tmpl)[i] = t;
}

// ---------------- transposes ------------------------------------------------
__global__ void transpose_k(const float* __restrict__ in, float* __restrict__ out,
                            int R, int Cc)
{
    __shared__ float tile[32][33];
    const size_t base = (size_t)blockIdx.z * R * Cc;
    const int c0 = blockIdx.x * 32, r0 = blockIdx.y * 32;
#pragma unroll
    for (int i = threadIdx.y; i < 32; i += 8)
        tile[i][threadIdx.x] = in[base + (size_t)(r0 + i) * Cc + c0 + threadIdx.x];
    __syncthreads();
#pragma unroll
    for (int i = threadIdx.y; i < 32; i += 8)
        out[base + (size_t)(c0 + i) * R + r0 + threadIdx.x] = tile[threadIdx.x][i];
}

// fp32 [R][Cc] -> fp16 [Cc][R] (weights, one-time)
__global__ void transpose_wh(const float* __restrict__ in, __half* __restrict__ out,
                             int R, int Cc)
{
    __shared__ float tile[32][33];
    const int c0 = blockIdx.x * 32, r0 = blockIdx.y * 32;
#pragma unroll
    for (int i = threadIdx.y; i < 32; i += 8)
        tile[i][threadIdx.x] = in[(size_t)(r0 + i) * Cc + c0 + threadIdx.x];
    __syncthreads();
#pragma unroll
    for (int i = threadIdx.y; i < 32; i += 8)
        out[(size_t)(c0 + i) * R + r0 + threadIdx.x] = __float2half_rn(tile[threadIdx.x][i]);
}

// V half of kv16 [l][2048] -> vT [d][l] per batch
__global__ void transpose_v(const __half* __restrict__ kv, __half* __restrict__ vT)
{
    __shared__ __half tile[32][33];
    const int d0 = blockIdx.x * 32, l0 = blockIdx.y * 32, z = blockIdx.z;
    const __half* src = kv + (size_t)z * L_ * 2 * D_ + D_;
    __half* dst = vT + (size_t)z * D_ * L_;
#pragma unroll
    for (int i = threadIdx.y; i < 32; i += 8)
        tile[i][threadIdx.x] = src[(size_t)(l0 + i) * 2 * D_ + d0 + threadIdx.x];
    __syncthreads();
#pragma unroll
    for (int i = threadIdx.y; i < 32; i += 8)
        dst[(size_t)(d0 + i) * L_ + l0 + threadIdx.x] = tile[threadIdx.x][i];
}

__global__ void bcast_tmpl(const float* __restrict__ tinit, float* __restrict__ tmpl)
{
    const size_t i = (size_t)blockIdx.x * 256 + threadIdx.x;
    tmpl[i] = tinit[i & ((size_t)N_ * D_ - 1)];
}

// out_attn[b][n][l] = (float)attnT[b][n][l] / cs[b][n]  (fully coalesced)
__global__ void attn_out(const __half* __restrict__ aT, const float* __restrict__ cs,
                         float* __restrict__ out)
{
    const int bn = blockIdx.x;
    const float s = 1.f / cs[bn];
    const __half2* src = (const __half2*)(aT + (size_t)bn * L_);
    float2* dst = (float2*)(out + (size_t)bn * L_);
    for (int i = threadIdx.x; i < L_ / 2; i += 256) {
        float2 v = __half22float2(src[i]);
        v.x *= s; v.y *= s;
        dst[i] = v;
    }
}

// ---------------- host orchestration ---------------------------------------
extern "C" void kernel_launch(void* const* d_in, const int* in_sizes, int n_in,
                              void* d_out, int out_size)
{
    const float* x       = (const float*)d_in[0];
    const float* tinit   = (const float*)d_in[1];
    const float* Wq      = (const float*)d_in[2];
    const float* Wk      = (const float*)d_in[3];
    const float* Wv      = (const float*)d_in[4];
    const float* ln_in_g = (const float*)d_in[5];
    const float* ln_in_b = (const float*)d_in[6];
    const float* ln_t_g  = (const float*)d_in[7];
    const float* ln_t_b  = (const float*)d_in[8];
    const float* ln_m_g  = (const float*)d_in[9];
    const float* ln_m_b  = (const float*)d_in[10];
    const float* W1      = (const float*)d_in[11];
    const float* b1      = (const float*)d_in[12];
    const float* W2      = (const float*)d_in[13];
    const float* b2      = (const float*)d_in[14];
    float* out = (float*)d_out;

    float *xn, *tmpl, *upd, *cs;
    __half *xn16, *kv16, *vT, *aT, *t16, *q16, *m16, *h16;
    __half *wqT, *wkvT, *w1T, *w2T;
    cudaGetSymbolAddress((void**)&xn,   g_xn);
    cudaGetSymbolAddress((void**)&xn16, g_xn16);
    cudaGetSymbolAddress((void**)&kv16, g_kv16);
    cudaGetSymbolAddress((void**)&vT,   g_vT);
    cudaGetSymbolAddress((void**)&aT,   g_aT);
    cudaGetSymbolAddress((void**)&tmpl, g_tmpl);
    cudaGetSymbolAddress((void**)&upd,  g_upd);
    cudaGetSymbolAddress((void**)&cs,   g_cs);
    cudaGetSymbolAddress((void**)&t16,  g_t16);
    cudaGetSymbolAddress((void**)&q16,  g_q16);
    cudaGetSymbolAddress((void**)&m16,  g_m16);
    cudaGetSymbolAddress((void**)&h16,  g_h16);
    cudaGetSymbolAddress((void**)&wqT,  g_wqT);
    cudaGetSymbolAddress((void**)&wkvT, g_wkvT);
    cudaGetSymbolAddress((void**)&w1T,  g_w1T);
    cudaGetSymbolAddress((void**)&w2T,  g_w2T);

    // smem bytes: 2*(AST+BST) halfs * 2
    const int SM_KV  = 2 * (128 * 40 + 256 * 40) * 2;  // 61440
    const int SM_64  = 2 * (64 * 40 + 256 * 40) * 2;   // 51200
    const int SM_UPD = SM_KV;

    cudaFuncSetAttribute(hgemm<128,256,0,0,0,1,1,0,0>, cudaFuncAttributeMaxDynamicSharedMemorySize, SM_KV);
    cudaFuncSetAttribute(hgemm<64,256,0,0,0,1,1,0,0>,  cudaFuncAttributeMaxDynamicSharedMemorySize, SM_64);
    cudaFuncSetAttribute(hgemm<64,256,0,0,0,0,1,0,1>,  cudaFuncAttributeMaxDynamicSharedMemorySize, SM_64);
    cudaFuncSetAttribute(hgemm<128,256,0,0,0,0,8,1,0>, cudaFuncAttributeMaxDynamicSharedMemorySize, SM_UPD);
    cudaFuncSetAttribute(hgemm<64,256,1,1,0,1,1,0,0>,  cudaFuncAttributeMaxDynamicSharedMemorySize, SM_64);
    cudaFuncSetAttribute(hgemm<64,256,1,0,1,0,1,0,0>,  cudaFuncAttributeMaxDynamicSharedMemorySize, SM_64);

    const dim3 tblk(32, 8);
    const float scale = 0.03125f;  // 1024^-0.5

    // one-time weight transposes fp32 -> fp16 [N][K]
    transpose_wh<<<dim3(D_ / 32, C_ / 32), tblk>>>(Wk, wkvT, C_, D_);
    transpose_wh<<<dim3(D_ / 32, C_ / 32), tblk>>>(Wv, wkvT + (size_t)D_ * C_, C_, D_);
    transpose_wh<<<dim3(D_ / 32, D_ / 32), tblk>>>(Wq, wqT, D_, D_);
    transpose_wh<<<dim3(MLP_ / 32, D_ / 32), tblk>>>(W1, w1T, D_, MLP_);
    transpose_wh<<<dim3(D_ / 32, MLP_ / 32), tblk>>>(W2, w2T, MLP_, D_);

    // x [B,C,L] -> xn [B,L,C] fp32, LN -> xn16 fp16
    transpose_k<<<dim3(L_ / 32, C_ / 32, B_), tblk>>>(x, xn, C_, L_);
    ln1024h<<<B_ * L_, 256>>>(xn, ln_in_g, ln_in_b, xn16);

    // [K|V] = xn16 @ wkvT^T -> kv16 fp16; then V transposed -> vT
    hgemm<128,256,0,0,0,1,1,0,0><<<dim3(2 * D_ / 256, (B_ * L_) / 128, 1), 256, SM_KV>>>(
        xn16, wkvT, nullptr, nullptr, kv16, nullptr,
        B_ * L_, 2 * D_, C_, C_, C_, 2 * D_, 0, 0, 0, 1.f);
    transpose_v<<<dim3(D_ / 32, L_ / 32, B_), tblk>>>(kv16, vT);

    bcast_tmpl<<<(B_ * N_ * D_) / 256, 256>>>(tinit, tmpl);

    for (int it = 0; it < TIT_; ++it) {
        // t = LN(t_prev) fp16; q = (t@Wq)*scale fp16
        ln1024h<<<B_ * N_, 256>>>(tmpl, ln_t_g, ln_t_b, t16);
        hgemm<64,256,0,0,0,1,1,0,0><<<dim3(D_ / 256, (B_ * N_) / 64, 1), 128, SM_64>>>(
            t16, wqT, nullptr, nullptr, q16, nullptr,
            B_ * N_, D_, D_, D_, D_, D_, 0, 0, 0, scale);

        zero_scratch<<<(B_ * N_ * D_) / 1024, 256>>>(upd, cs);

        // fused logits+softmax: A=K (kv16, lda 2048), B=q16 -> attn^T fp16 + colsum
        hgemm<64,256,0,0,0,0,1,0,1><<<dim3(1, L_ / 64, B_), 128, SM_64>>>(
            kv16, q16, nullptr, nullptr, aT, cs,
            L_, N_, D_, 2 * D_, D_, L_,
            (long long)L_ * 2 * D_, (long long)N_ * D_, (long long)N_ * L_, 1.f);

        // upd = attn^T @ V  (A=aT [n][l], B=vT [d][l]), split-K x8 atomic
        hgemm<128,256,0,0,0,0,8,1,0><<<dim3(D_ / 256, N_ / 128, B_ * 8), 256, SM_UPD>>>(
            aT, vT, nullptr, nullptr, upd, nullptr,
            N_, D_, L_, L_, L_, D_,
            (long long)N_ * L_, (long long)D_ * L_, (long long)N_ * D_, 1.f);

        // templates += upd / colsum
        apply_update<<<(B_ * N_ * D_) / 1024, 256>>>(tmpl, upd, cs);

        // m = LN(templates) fp16; templates += relu(m@W1+b1)@W2 + b2
        ln1024h<<<B_ * N_, 256>>>(tmpl, ln_m_g, ln_m_b, m16);
        hgemm<64,256,1,1,0,1,1,0,0><<<dim3(MLP_ / 256, (B_ * N_) / 64, 1), 128, SM_64>>>(
            m16, w1T, b1, nullptr, h16, nullptr,
            B_ * N_, MLP_, D_, D_, D_, MLP_, 0, 0, 0, 1.f);
        hgemm<64,256,1,0,1,0,1,0,0><<<dim3(D_ / 256, (B_ * N_) / 64, 1), 128, SM_64>>>(
            h16, w2T, b2, tmpl, tmpl, nullptr,
            B_ * N_, D_, MLP_, MLP_, MLP_, D_, 0, 0, (long long)0, 1.f);
    }

    // out_templates [B,D,N] = transpose(tmpl); out_attn from attn^T directly
    transpose_k<<<dim3(D_ / 32, N_ / 32, B_), tblk>>>(tmpl, out, N_, D_);
    attn_out<<<B_ * N_, 256>>>(aT, cs, out + (size_t)B_ * D_ * N_);
}

// round 14
// speedup vs baseline: 2.4101x; 1.0017x over previous
#include <cuda_runtime.h>
#include <cuda_fp16.h>
#include <cstddef>

#define B_    8
#define L_    4096
#define C_    1024
#define D_    1024
#define N_    256
#define MLP_  512
#define TIT_  6

// ---------------- scratch (device globals; no allocation allowed) ----------
__device__ float  g_xn  [(size_t)B_ * L_ * C_];
__device__ __half g_xn16[(size_t)B_ * L_ * C_];
__device__ __half g_kv16[(size_t)B_ * L_ * 2 * D_];  // [l][0:1024]=K, [l][1024:2048]=V
__device__ __half g_vT  [(size_t)B_ * D_ * L_];      // V transposed [d][l]
__device__ __half g_aT  [(size_t)B_ * N_ * L_];      // attn^T [n][l], fp16
__device__ float  g_tmpl[B_ * N_ * D_];
__device__ float  g_upd [B_ * N_ * D_];
__device__ float  g_cs  [B_ * N_];
__device__ __half g_t16 [B_ * N_ * D_];
__device__ __half g_q16 [B_ * N_ * D_];
__device__ __half g_m16 [B_ * N_ * D_];
__device__ __half g_h16 [B_ * N_ * MLP_];
__device__ __half g_wqT [D_ * D_];
__device__ __half g_wkvT[2 * D_ * C_];
__device__ __half g_w1T [MLP_ * D_];
__device__ __half g_w2T [D_ * MLP_];

__device__ __forceinline__ void cp16(void* smem_dst, const void* gmem_src) {
    unsigned s = (unsigned)__cvta_generic_to_shared(smem_dst);
    asm volatile("cp.async.cg.shared.global [%0], [%1], 16;\n"
                 :: "r"(s), "l"(gmem_src));
}

// ---------------- fp16 tensor-core GEMM, cp.async double-buffered -----------
// C[M,N] = alpha * A B^T (+bias)(relu)(+resid) | atomic partials | fused softmax
// A [M][K] and B [N][K], BOTH row-major k-contiguous fp16.
// CTA tile BM x BN x 32; warp tile 64x64 via mma.m16n8k16.f16; fp32 accum.
// smem pitch 40 halfs per 32-half row (conflict-free half2 fragment loads).
// SMAX (BM=64, BN=256=N_): softmax over N per row, writes attn^T fp16 [n][l]
// via smem-staged transpose; fp32 colsum atomics into cs.
template<int BM, int BN, int BIAS, int RELU, int RESID, int OUT16,
         int SPLITK, int ATOMIC, int SMAX>
__global__ void __launch_bounds__((BM / 64) * (BN / 64) * 32,
                                  ((BM / 64) * (BN / 64) * 32 == 128) ? 2 : 1)
hgemm(const __half* __restrict__ A, const __half* __restrict__ Bm,
      const float* __restrict__ bias, const float* __restrict__ Rm,
      void* __restrict__ Cv, float* __restrict__ cs,
      int M, int N, int K, int lda, int ldb, int ldc,
      long long sA, long long sB, long long sC, float alpha)
{
    constexpr int WM = BM / 64, WN = BN / 64;
    constexpr int THREADS = WM * WN * 32;
    constexpr int AST = BM * 40;             // halfs per stage
    constexpr int BST = BN * 40;
    constexpr int NA = BM * 4 / THREADS;     // cp16 per thread for A
    constexpr int NB = BN * 4 / THREADS;
    extern __shared__ __half sm16[];

    int bz = blockIdx.z, batch = bz, koff = 0;
    if (SPLITK > 1) { batch = bz / SPLITK; koff = (bz % SPLITK) * (K / SPLITK); }
    A  += (size_t)batch * sA + koff;
    Bm += (size_t)batch * sB + koff;
    const float* Rp = RESID ? (Rm + (size_t)batch * sC) : nullptr;

    const int m0 = blockIdx.y * BM, n0 = blockIdx.x * BN;
    const int tid = threadIdx.x, lane = tid & 31, wid = tid >> 5;
    const int wm = (wid % WM) * 64, wn = (wid / WM) * 64;
    const int g = lane >> 2, tig = lane & 3;

    float acc[4][8][4] = {};

    auto load_stage = [&](int k0, int s) {
        __half* Ad = sm16 + s * AST;
        __half* Bd = sm16 + 2 * AST + s * BST;
#pragma unroll
        for (int i = 0; i < NA; i++) {
            const int idx = tid + i * THREADS;
            const int row = idx >> 2, kc = (idx & 3) * 8;
            cp16(Ad + row * 40 + kc, A + (size_t)(m0 + row) * lda + k0 + kc);
        }
#pragma unroll
        for (int i = 0; i < NB; i++) {
            const int idx = tid + i * THREADS;
            const int row = idx >> 2, kc = (idx & 3) * 8;
            cp16(Bd + row * 40 + kc, Bm + (size_t)(n0 + row) * ldb + k0 + kc);
        }
        asm volatile("cp.async.commit_group;\n");
    };

    auto compute = [&](int s) {
        // half2 views; pitch = 20 half2 per row
        const unsigned* Ah = (const unsigned*)(sm16 + s * AST);
        const unsigned* Bh = (const unsigned*)(sm16 + 2 * AST + s * BST);
#pragma unroll
        for (int ks = 0; ks < 2; ks++) {           // two k16 steps per 32-tile
            const int kb = ks * 8;                 // half2 offset
            unsigned a[4][4], b[8][2];
#pragma unroll
            for (int mt = 0; mt < 4; mt++) {
                const int r = wm + mt * 16 + g;
                a[mt][0] = Ah[r * 20 + kb + tig];
                a[mt][1] = Ah[(r + 8) * 20 + kb + tig];
                a[mt][2] = Ah[r * 20 + kb + 4 + tig];
                a[mt][3] = Ah[(r + 8) * 20 + kb + 4 + tig];
            }
#pragma unroll
            for (int nt = 0; nt < 8; nt++) {
                const int c = wn + nt * 8 + g;
                b[nt][0] = Bh[c * 20 + kb + tig];
                b[nt][1] = Bh[c * 20 + kb + 4 + tig];
            }
#pragma unroll
            for (int mt = 0; mt < 4; mt++)
#pragma unroll
                for (int nt = 0; nt < 8; nt++)
                    asm volatile(
                        "mma.sync.aligned.m16n8k16.row.col.f32.f16.f16.f32 "
                        "{%0,%1,%2,%3}, {%4,%5,%6,%7}, {%8,%9}, {%0,%1,%2,%3};"
                        : "+f"(acc[mt][nt][0]), "+f"(acc[mt][nt][1]),
                          "+f"(acc[mt][nt][2]), "+f"(acc[mt][nt][3])
                        : "r"(a[mt][0]), "r"(a[mt][1]), "r"(a[mt][2]), "r"(a[mt][3]),
                          "r"(b[nt][0]), "r"(b[nt][1]));
        }
    };

    load_stage(0, 0);
    const int T = ((SPLITK > 1) ? K / SPLITK : K) >> 5;
    for (int t = 0; t < T; t++) {
        asm volatile("cp.async.wait_group 0;\n");
        __syncthreads();
        if (t + 1 < T) load_stage((t + 1) << 5, (t + 1) & 1);
        compute(t & 1);
    }

    if (SMAX) {
        // BM=64, BN=256: full softmax row per CTA; WM=1, wm=0.
        float* red = (float*)sm16;              // [64][WN]
        float fmx[4][2], fsm[4][2];
        __syncthreads();
        // ---- row max ----
#pragma unroll
        for (int mt = 0; mt < 4; mt++) {
            float h0 = -1e30f, h1 = -1e30f;
#pragma unroll
            for (int nt = 0; nt < 8; nt++) {
                h0 = fmaxf(h0, fmaxf(acc[mt][nt][0], acc[mt][nt][1]));
                h1 = fmaxf(h1, fmaxf(acc[mt][nt][2], acc[mt][nt][3]));
            }
            h0 = fmaxf(h0, __shfl_xor_sync(0xffffffffu, h0, 1));
            h0 = fmaxf(h0, __shfl_xor_sync(0xffffffffu, h0, 2));
            h1 = fmaxf(h1, __shfl_xor_sync(0xffffffffu, h1, 1));
            h1 = fmaxf(h1, __shfl_xor_sync(0xffffffffu, h1, 2));
            fmx[mt][0] = h0; fmx[mt][1] = h1;
        }
        if (tig == 0)
#pragma unroll
            for (int mt = 0; mt < 4; mt++) {
                red[(mt * 16 + g) * WN + wid] = fmx[mt][0];
                red[(mt * 16 + g + 8) * WN + wid] = fmx[mt][1];
            }
        __syncthreads();
#pragma unroll
        for (int mt = 0; mt < 4; mt++) {
            float h0 = -1e30f, h1 = -1e30f;
#pragma unroll
            for (int w = 0; w < WN; w++) {
                h0 = fmaxf(h0, red[(mt * 16 + g) * WN + w]);
                h1 = fmaxf(h1, red[(mt * 16 + g + 8) * WN + w]);
            }
            fmx[mt][0] = h0; fmx[mt][1] = h1;
        }
        __syncthreads();
        // ---- exp + row sum ----
#pragma unroll
        for (int mt = 0; mt < 4; mt++) {
            float s0 = 0.f, s1 = 0.f;
#pragma unroll
            for (int nt = 0; nt < 8; nt++) {
                acc[mt][nt][0] = __expf(acc[mt][nt][0] - fmx[mt][0]);
                acc[mt][nt][1] = __expf(acc[mt][nt][1] - fmx[mt][0]);
                acc[mt][nt][2] = __expf(acc[mt][nt][2] - fmx[mt][1]);
                acc[mt][nt][3] = __expf(acc[mt][nt][3] - fmx[mt][1]);
                s0 += acc[mt][nt][0] + acc[mt][nt][1];
                s1 += acc[mt][nt][2] + acc[mt][nt][3];
            }
            s0 += __shfl_xor_sync(0xffffffffu, s0, 1);
            s0 += __shfl_xor_sync(0xffffffffu, s0, 2);
            s1 += __shfl_xor_sync(0xffffffffu, s1, 1);
            s1 += __shfl_xor_sync(0xffffffffu, s1, 2);
            fsm[mt][0] = s0; fsm[mt][1] = s1;
        }
        if (tig == 0)
#pragma unroll
            for (int mt = 0; mt < 4; mt++) {
                red[(mt * 16 + g) * WN + wid] = fsm[mt][0];
                red[(mt * 16 + g + 8) * WN + wid] = fsm[mt][1];
            }
        __syncthreads();
#pragma unroll
        for (int mt = 0; mt < 4; mt++) {
            float s0 = 0.f, s1 = 0.f;
#pragma unroll
            for (int w = 0; w < WN; w++) {
                s0 += red[(mt * 16 + g) * WN + w];
                s1 += red[(mt * 16 + g + 8) * WN + w];
            }
            fsm[mt][0] = 1.f / s0; fsm[mt][1] = 1.f / s1;
        }
        __syncthreads();   // red region about to be reused as transpose tile
        // ---- normalize (+1e-8), stage transposed to smem, colsum fp32 ----
        __half* tt = sm16;                      // [256][80] halfs (pitch 80)
        float csum[8][2];
#pragma unroll
        for (int nt = 0; nt < 8; nt++) { csum[nt][0] = 0.f; csum[nt][1] = 0.f; }
#pragma unroll
        for (int mt = 0; mt < 4; mt++) {
            const int l0 = mt * 16 + g, l1 = l0 + 8;
#pragma unroll
            for (int nt = 0; nt < 8; nt++) {
                const int c = wn + nt * 8 + tig * 2;
                const float a0 = acc[mt][nt][0] * fsm[mt][0] + 1e-8f;
                const float a1 = acc[mt][nt][1] * fsm[mt][0] + 1e-8f;
                const float a2 = acc[mt][nt][2] * fsm[mt][1] + 1e-8f;
                const float a3 = acc[mt][nt][3] * fsm[mt][1] + 1e-8f;
                tt[c * 80 + l0]       = __float2half_rn(a0);
                tt[(c + 1) * 80 + l0] = __float2half_rn(a1);
                tt[c * 80 + l1]       = __float2half_rn(a2);
                tt[(c + 1) * 80 + l1] = __float2half_rn(a3);
                csum[nt][0] += a0 + a2;
                csum[nt][1] += a1 + a3;
            }
        }
        float* csp = cs + batch * N_;
#pragma unroll
        for (int nt = 0; nt < 8; nt++) {
            float s0 = csum[nt][0], s1 = csum[nt][1];
            s0 += __shfl_xor_sync(0xffffffffu, s0, 4);
            s0 += __shfl_xor_sync(0xffffffffu, s0, 8);
            s0 += __shfl_xor_sync(0xffffffffu, s0, 16);
            s1 += __shfl_xor_sync(0xffffffffu, s1, 4);
            s1 += __shfl_xor_sync(0xffffffffu, s1, 8);
            s1 += __shfl_xor_sync(0xffffffffu, s1, 16);
            if (lane < 4) {
                const int c = wn + nt * 8 + lane * 2;
                atomicAdd(csp + c, s0);
                atomicAdd(csp + c + 1, s1);
            }
        }
        __syncthreads();
        // ---- coalesced store: attn^T [n][l], 64 halfs per n-row ----
        __half* Ao = (__half*)Cv + (size_t)batch * sC;
        for (int n = tid; n < 256; n += THREADS) {
            const uint4* s4 = (const uint4*)(tt + n * 80);
            uint4* d4 = (uint4*)(Ao + (size_t)n * ldc + m0);
#pragma unroll
            for (int j = 0; j < 8; j++) d4[j] = s4[j];
        }
        return;
    }

    // ---------------- standard epilogues ----------------
    if (ATOMIC) {
        float* Cm = (float*)Cv + (size_t)batch * sC;
#pragma unroll
        for (int mt = 0; mt < 4; mt++) {
            const int r0 = m0 + wm + mt * 16 + g, r1 = r0 + 8;
#pragma unroll
            for (int nt = 0; nt < 8; nt++) {
                const int c = n0 + wn + nt * 8 + tig * 2;
                atomicAdd(Cm + (size_t)r0 * ldc + c,     acc[mt][nt][0]);
                atomicAdd(Cm + (size_t)r0 * ldc + c + 1, acc[mt][nt][1]);
                atomicAdd(Cm + (size_t)r1 * ldc + c,     acc[mt][nt][2]);
                atomicAdd(Cm + (size_t)r1 * ldc + c + 1, acc[mt][nt][3]);
            }
        }
        return;
    }
#pragma unroll
    for (int mt = 0; mt < 4; mt++) {
        const int r0 = m0 + wm + mt * 16 + g, r1 = r0 + 8;
#pragma unroll
        for (int nt = 0; nt < 8; nt++) {
            const int c = n0 + wn + nt * 8 + tig * 2;
            float v0 = acc[mt][nt][0] * alpha, v1 = acc[mt][nt][1] * alpha;
            float v2 = acc[mt][nt][2] * alpha, v3 = acc[mt][nt][3] * alpha;
            if (BIAS) {
                const float bx = bias[c], by = bias[c + 1];
                v0 += bx; v1 += by; v2 += bx; v3 += by;
            }
            if (RELU) {
                v0 = fmaxf(v0, 0.f); v1 = fmaxf(v1, 0.f);
                v2 = fmaxf(v2, 0.f); v3 = fmaxf(v3, 0.f);
            }
            if (RESID) {
                const float2 p = *(const float2*)(Rp + (size_t)r0 * ldc + c);
                const float2 q = *(const float2*)(Rp + (size_t)r1 * ldc + c);
                v0 += p.x; v1 += p.y; v2 += q.x; v3 += q.y;
            }
            if (OUT16) {
                __half* C16 = (__half*)Cv;
                *(__half2*)(C16 + (size_t)r0 * ldc + c) = __floats2half2_rn(v0, v1);
                *(__half2*)(C16 + (size_t)r1 * ldc + c) = __floats2half2_rn(v2, v3);
            } else {
                float* Cm = (float*)Cv + (size_t)batch * sC;
                float2 o0; o0.x = v0; o0.y = v1;
                float2 o1; o1.x = v2; o1.y = v3;
                *(float2*)(Cm + (size_t)r0 * ldc + c) = o0;
                *(float2*)(Cm + (size_t)r1 * ldc + c) = o1;
            }
        }
    }
}

// ---------------- LayerNorm over 1024-wide rows, fp16 output ----------------
__global__ void __launch_bounds__(256) ln1024h(
    const float* __restrict__ in, const float* __restrict__ g,
    const float* __restrict__ b, __half* __restrict__ out)
{
    __shared__ float sh[8];
    __shared__ float s_mean, s_rstd;
    const size_t row = blockIdx.x;
    const int t = threadIdx.x;
    const float4 v = ((const float4*)(in + row * 1024))[t];

    float s = v.x + v.y + v.z + v.w;
#pragma unroll
    for (int o = 16; o; o >>= 1) s += __shfl_xor_sync(0xffffffffu, s, o);
    if ((t & 31) == 0) sh[t >> 5] = s;
    __syncthreads();
    if (t == 0) {
        float tt = 0.f;
#pragma unroll
        for (int i = 0; i < 8; i++) tt += sh[i];
        s_mean = tt * (1.f / 1024.f);
    }
    __syncthreads();
    const float mean = s_mean;
    const float dx = v.x - mean, dy = v.y - mean, dz = v.z - mean, dw = v.w - mean;

    float q = dx * dx + dy * dy + dz * dz + dw * dw;
#pragma unroll
    for (int o = 16; o; o >>= 1) q += __shfl_xor_sync(0xffffffffu, q, o);
    __syncthreads();
    if ((t & 31) == 0) sh[t >> 5] = q;
    __syncthreads();
    if (t == 0) {
        float tt = 0.f;
#pragma unroll
        for (int i = 0; i < 8; i++) tt += sh[i];
        s_rstd = rsqrtf(tt * (1.f / 1024.f) + 1e-5f);
    }
    __syncthreads();
    const float rstd = s_rstd;

    const float4 gv = ((const float4*)g)[t];
    const float4 bv = ((const float4*)b)[t];
    __half2* oh = (__half2*)(out + row * 1024) + t * 2;
    oh[0] = __floats2half2_rn(dx * rstd * gv.x + bv.x, dy * rstd * gv.y + bv.y);
    oh[1] = __floats2half2_rn(dz * rstd * gv.z + bv.z, dw * rstd * gv.w + bv.w);
}

// zero colsum [B*N] and upd [B*N*D]
__global__ void zero_scratch(float* __restrict__ upd, float* __restrict__ cs)
{
    const size_t i = (size_t)blockIdx.x * 256 + threadIdx.x;
    ((float4*)upd)[i] = make_float4(0.f, 0.f, 0.f, 0.f);
    if (i < B_ * N_) cs[i] = 0.f;
}

// tmpl += upd / colsum[row]  (the folded L-renorm)
__global__ void apply_update(float* __restrict__ tmpl, const float* __restrict__ upd,
                             const float* __restrict__ cs)
{
    const size_t i = (size_t)blockIdx.x * 256 + threadIdx.x;
    const int row = (int)(i / (D_ / 4));
    const float s = 1.f / cs[row];
    const float4 u = ((const float4*)upd)[i];
    float4 t = ((float4*)tmpl)[i];
    t.x += u.x * s; t.y += u.y * s; t.z += u.z * s; t.w += u.w * s;
    ((float4*)tmpl)[i] = t;
}

// ---------------- transposes ------------------------------------------------
__global__ void transpose_k(const float* __restrict__ in, float* __restrict__ out,
                            int R, int Cc)
{
    __shared__ float tile[32][33];
    const size_t base = (size_t)blockIdx.z * R * Cc;
    const int c0 = blockIdx.x * 32, r0 = blockIdx.y * 32;
#pragma unroll
    for (int i = threadIdx.y; i < 32; i += 8)
        tile[i][threadIdx.x] = in[base + (size_t)(r0 + i) * Cc + c0 + threadIdx.x];
    __syncthreads();
#pragma unroll
    for (int i = threadIdx.y; i < 32; i += 8)
        out[base + (size_t)(c0 + i) * R + r0 + threadIdx.x] = tile[threadIdx.x][i];
}

// fp32 [R][Cc] -> fp16 [Cc][R] (weights, one-time)
__global__ void transpose_wh(const float* __restrict__ in, __half* __restrict__ out,
                             int R, int Cc)
{
    __shared__ float tile[32][33];
    const int c0 = blockIdx.x * 32, r0 = blockIdx.y * 32;
#pragma unroll
    for (int i = threadIdx.y; i < 32; i += 8)
        tile[i][threadIdx.x] = in[(size_t)(r0 + i) * Cc + c0 + threadIdx.x];
    __syncthreads();
#pragma unroll
    for (int i = threadIdx.y; i < 32; i += 8)
        out[(size_t)(c0 + i) * R + r0 + threadIdx.x] = __float2half_rn(tile[threadIdx.x][i]);
}

// V half of kv16 [l][2048] -> vT [d][l] per batch
__global__ void transpose_v(const __half* __restrict__ kv, __half* __restrict__ vT)
{
    __shared__ __half tile[32][33];
    const int d0 = blockIdx.x * 32, l0 = blockIdx.y * 32, z = blockIdx.z;
    const __half* src = kv + (size_t)z * L_ * 2 * D_ + D_;
    __half* dst = vT + (size_t)z * D_ * L_;
#pragma unroll
    for (int i = threadIdx.y; i < 32; i += 8)
        tile[i][threadIdx.x] = src[(size_t)(l0 + i) * 2 * D_ + d0 + threadIdx.x];
    __syncthreads();
#pragma unroll
    for (int i = threadIdx.y; i < 32; i += 8)
        dst[(size_t)(d0 + i) * L_ + l0 + threadIdx.x] = tile[threadIdx.x][i];
}

__global__ void bcast_tmpl(const float* __restrict__ tinit, float* __restrict__ tmpl)
{
    const size_t i = (size_t)blockIdx.x * 256 + threadIdx.x;
    tmpl[i] = tinit[i & ((size_t)N_ * D_ - 1)];
}

// out_attn[b][n][l] = (float)attnT[b][n][l] / cs[b][n]  (fully coalesced)
__global__ void attn_out(const __half* __restrict__ aT, const float* __restrict__ cs,
                         float* __restrict__ out)
{
    const int bn = blockIdx.x;
    const float s = 1.f / cs[bn];
    const __half2* src = (const __half2*)(aT + (size_t)bn * L_);
    float2* dst = (float2*)(out + (size_t)bn * L_);
    for (int i = threadIdx.x; i < L_ / 2; i += 256) {
        float2 v = __half22float2(src[i]);
        v.x *= s; v.y *= s;
        dst[i] = v;
    }
}

// ---------------- host orchestration ---------------------------------------
extern "C" void kernel_launch(void* const* d_in, const int* in_sizes, int n_in,
                              void* d_out, int out_size)
{
    const float* x       = (const float*)d_in[0];
    const float* tinit   = (const float*)d_in[1];
    const float* Wq      = (const float*)d_in[2];
    const float* Wk      = (const float*)d_in[3];
    const float* Wv      = (const float*)d_in[4];
    const float* ln_in_g = (const float*)d_in[5];
    const float* ln_in_b = (const float*)d_in[6];
    const float* ln_t_g  = (const float*)d_in[7];
    const float* ln_t_b  = (const float*)d_in[8];
    const float* ln_m_g  = (const float*)d_in[9];
    const float* ln_m_b  = (const float*)d_in[10];
    const float* W1      = (const float*)d_in[11];
    const float* b1      = (const float*)d_in[12];
    const float* W2      = (const float*)d_in[13];
    const float* b2      = (const float*)d_in[14];
    float* out = (float*)d_out;

    float *xn, *tmpl, *upd, *cs;
    __half *xn16, *kv16, *vT, *aT, *t16, *q16, *m16, *h16;
    __half *wqT, *wkvT, *w1T, *w2T;
    cudaGetSymbolAddress((void**)&xn,   g_xn);
    cudaGetSymbolAddress((void**)&xn16, g_xn16);
    cudaGetSymbolAddress((void**)&kv16, g_kv16);
    cudaGetSymbolAddress((void**)&vT,   g_vT);
    cudaGetSymbolAddress((void**)&aT,   g_aT);
    cudaGetSymbolAddress((void**)&tmpl, g_tmpl);
    cudaGetSymbolAddress((void**)&upd,  g_upd);
    cudaGetSymbolAddress((void**)&cs,   g_cs);
    cudaGetSymbolAddress((void**)&t16,  g_t16);
    cudaGetSymbolAddress((void**)&q16,  g_q16);
    cudaGetSymbolAddress((void**)&m16,  g_m16);
    cudaGetSymbolAddress((void**)&h16,  g_h16);
    cudaGetSymbolAddress((void**)&wqT,  g_wqT);
    cudaGetSymbolAddress((void**)&wkvT, g_wkvT);
    cudaGetSymbolAddress((void**)&w1T,  g_w1T);
    cudaGetSymbolAddress((void**)&w2T,  g_w2T);

    // smem bytes: 2*(AST+BST) halfs * 2
    const int SM_KV  = 2 * (128 * 40 + 256 * 40) * 2;  // 61440
    const int SM_64  = 2 * (64 * 40 + 256 * 40) * 2;   // 51200
    const int SM_UPD = SM_KV;

    cudaFuncSetAttribute(hgemm<128,256,0,0,0,1,1,0,0>, cudaFuncAttributeMaxDynamicSharedMemorySize, SM_KV);
    cudaFuncSetAttribute(hgemm<64,256,0,0,0,1,1,0,0>,  cudaFuncAttributeMaxDynamicSharedMemorySize, SM_64);
    cudaFuncSetAttribute(hgemm<64,256,0,0,0,0,1,0,1>,  cudaFuncAttributeMaxDynamicSharedMemorySize, SM_64);
    cudaFuncSetAttribute(hgemm<128,256,0,0,0,0,8,1,0>, cudaFuncAttributeMaxDynamicSharedMemorySize, SM_UPD);
    cudaFuncSetAttribute(hgemm<64,256,1,1,0,1,1,0,0>,  cudaFuncAttributeMaxDynamicSharedMemorySize, SM_64);
    cudaFuncSetAttribute(hgemm<64,256,1,0,1,0,1,0,0>,  cudaFuncAttributeMaxDynamicSharedMemorySize, SM_64);

    const dim3 tblk(32, 8);
    const float scale = 0.03125f;  // 1024^-0.5

    // one-time weight transposes fp32 -> fp16 [N][K]
    transpose_wh<<<dim3(D_ / 32, C_ / 32), tblk>>>(Wk, wkvT, C_, D_);
    transpose_wh<<<dim3(D_ / 32, C_ / 32), tblk>>>(Wv, wkvT + (size_t)D_ * C_, C_, D_);
    transpose_wh<<<dim3(D_ / 32, D_ / 32), tblk>>>(Wq, wqT, D_, D_);
    transpose_wh<<<dim3(MLP_ / 32, D_ / 32), tblk>>>(W1, w1T, D_, MLP_);
    transpose_wh<<<dim3(D_ / 32, MLP_ / 32), tblk>>>(W2, w2T, MLP_, D_);

    // x [B,C,L] -> xn [B,L,C] fp32, LN -> xn16 fp16
    transpose_k<<<dim3(L_ / 32, C_ / 32, B_), tblk>>>(x, xn, C_, L_);
    ln1024h<<<B_ * L_, 256>>>(xn, ln_in_g, ln_in_b, xn16);

    // [K|V] = xn16 @ wkvT^T -> kv16 fp16; then V transposed -> vT
    hgemm<128,256,0,0,0,1,1,0,0><<<dim3(2 * D_ / 256, (B_ * L_) / 128, 1), 256, SM_KV>>>(
        xn16, wkvT, nullptr, nullptr, kv16, nullptr,
        B_ * L_, 2 * D_, C_, C_, C_, 2 * D_, 0, 0, 0, 1.f);
    transpose_v<<<dim3(D_ / 32, L_ / 32, B_), tblk>>>(kv16, vT);

    bcast_tmpl<<<(B_ * N_ * D_) / 256, 256>>>(tinit, tmpl);

    for (int it = 0; it < TIT_; ++it) {
        // t = LN(t_prev) fp16; q = (t@Wq)*scale fp16
        ln1024h<<<B_ * N_, 256>>>(tmpl, ln_t_g, ln_t_b, t16);
        hgemm<64,256,0,0,0,1,1,0,0><<<dim3(D_ / 256, (B_ * N_) / 64, 1), 128, SM_64>>>(
            t16, wqT, nullptr, nullptr, q16, nullptr,
            B_ * N_, D_, D_, D_, D_, D_, 0, 0, 0, scale);

        zero_scratch<<<(B_ * N_ * D_) / 1024, 256>>>(upd, cs);

        // fused logits+softmax: A=K (kv16, lda 2048), B=q16 -> attn^T fp16 + colsum
        hgemm<64,256,0,0,0,0,1,0,1><<<dim3(1, L_ / 64, B_), 128, SM_64>>>(
            kv16, q16, nullptr, nullptr, aT, cs,
            L_, N_, D_, 2 * D_, D_, L_,
            (long long)L_ * 2 * D_, (long long)N_ * D_, (long long)N_ * L_, 1.f);

        // upd = attn^T @ V  (A=aT [n][l], B=vT [d][l]), split-K x8 atomic
        hgemm<128,256,0,0,0,0,8,1,0><<<dim3(D_ / 256, N_ / 128, B_ * 8), 256, SM_UPD>>>(
            aT, vT, nullptr, nullptr, upd, nullptr,
            N_, D_, L_, L_, L_, D_,
            (long long)N_ * L_, (long long)D_ * L_, (long long)N_ * D_, 1.f);

        // templates += upd / colsum
        apply_update<<<(B_ * N_ * D_) / 1024, 256>>>(tmpl, upd, cs);

        // m = LN(templates) fp16; templates += relu(m@W1+b1)@W2 + b2
        ln1024h<<<B_ * N_, 256>>>(tmpl, ln_m_g, ln_m_b, m16);
        hgemm<64,256,1,1,0,1,1,0,0><<<dim3(MLP_ / 256, (B_ * N_) / 64, 1), 128, SM_64>>>(
            m16, w1T, b1, nullptr, h16, nullptr,
            B_ * N_, MLP_, D_, D_, D_, MLP_, 0, 0, 0, 1.f);
        hgemm<64,256,1,0,1,0,1,0,0><<<dim3(D_ / 256, (B_ * N_) / 64, 1), 128, SM_64>>>(
            h16, w2T, b2, tmpl, tmpl, nullptr,
            B_ * N_, D_, MLP_, MLP_, MLP_, D_, 0, 0, (long long)0, 1.f);
    }

    // out_templates [B,D,N] = transpose(tmpl); out_attn from attn^T directly
    transpose_k<<<dim3(D_ / 32, N_ / 32, B_), tblk>>>(tmpl, out, N_, D_);
    attn_out<<<B_ * N_, 256>>>(aT, cs, out + (size_t)B_ * D_ * N_);
}